// round 9
// baseline (speedup 1.0000x reference)
#include <cuda_runtime.h>
#include <math.h>

#define NHID 64
#define NMAX 400000
#define NXMAX 100000
#define NNZCAP 2200000
#define BN_EPS 1e-5f

typedef unsigned long long u64;

// ---------------- scratch (device globals; no allocations) ----------------
__device__ __align__(256) float  g_dn[NMAX];
__device__ __align__(256) float  g_de[NMAX];
__device__ __align__(256) float  g_h [NMAX * NHID];
__device__ __align__(256) float  g_mn[NMAX * NHID];
__device__ __align__(256) float  g_me[NMAX * NHID];
__device__ __align__(256) float  g_t [NXMAX * NHID];
__device__ double g_sum[NHID];
__device__ double g_sumsq[NHID];
__device__ __align__(256) int   g_cnt_n[NMAX], g_cnt_e[NMAX];
__device__ __align__(256) int   g_cur_n[NMAX], g_cur_e[NMAX];
__device__ __align__(256) int   g_start_n[NMAX], g_start_e[NMAX];
__device__ __align__(256) int2  g_pkn[NNZCAP], g_pke[NNZCAP];
__device__ int g_bsum_n[256], g_bsum_e[256], g_boff_n[256], g_boff_e[256];
// software grid barrier state (monotonic generation; cnt returns to 0)
__device__ int g_bar_cnt = 0;
__device__ int g_bar_gen = 0;

// ---------------- helpers ----------------
__device__ __forceinline__ u64 pack2(float lo, float hi) {
    u64 r; asm("mov.b64 %0, {%1,%2};" : "=l"(r) : "f"(lo), "f"(hi)); return r;
}
__device__ __forceinline__ float2 unpack2(u64 v) {
    float2 r; asm("mov.b64 {%0,%1}, %2;" : "=f"(r.x), "=f"(r.y) : "l"(v)); return r;
}
__device__ __forceinline__ void fma2(u64& acc, u64 a, u64 b) {
    asm("fma.rn.f32x2 %0, %1, %2, %0;" : "+l"(acc) : "l"(a), "l"(b));
}
__device__ __forceinline__ float sigmf(float x) {
    return __fdividef(1.0f, 1.0f + __expf(-x));
}
__device__ __forceinline__ float tanhfast(float x) {
    return 2.0f * sigmf(2.0f * x) - 1.0f;
}

// software grid barrier: all gridDim.x blocks MUST be co-resident
__device__ __forceinline__ void gridbar() {
    __threadfence();
    __syncthreads();
    if (threadIdx.x == 0) {
        int old = atomicAdd(&g_bar_gen, 0);
        if (atomicAdd(&g_bar_cnt, 1) == (int)gridDim.x - 1) {
            atomicExch(&g_bar_cnt, 0);
            __threadfence();
            atomicAdd(&g_bar_gen, 1);
        } else {
            while (atomicAdd(&g_bar_gen, 0) == old) { }
        }
    }
    __syncthreads();
}

// ============ K1: build — copy/zero, hist, scan, scatter (persistent) ====
__global__ void __launch_bounds__(256) k_build(
    const float4* __restrict__ h_src,
    const int* __restrict__ nr, const int* __restrict__ nc,
    const float* __restrict__ nv, int nnzN,
    const int* __restrict__ er, const int* __restrict__ ec,
    const float* __restrict__ ev, int nnzE,
    int N, int Nold) {
    int tid = threadIdx.x;
    int gt = blockIdx.x * 256 + tid;
    int gs = gridDim.x * 256;
    int tot = nnzN + nnzE;

    // phase 0: copy h_in into g_h, zero counters/diags/stats
    {
        float4* dst = reinterpret_cast<float4*>(g_h);
        int n4 = Nold * (NHID / 4);
        for (int j = gt; j < n4; j += gs) dst[j] = h_src[j];
        for (int j = gt; j < N; j += gs) {
            g_dn[j] = 0.f; g_de[j] = 0.f;
            g_cnt_n[j] = 0; g_cnt_e[j] = 0;
            g_cur_n[j] = 0; g_cur_e[j] = 0;
        }
        if (gt < NHID) { g_sum[gt] = 0.0; g_sumsq[gt] = 0.0; }
    }
    gridbar();

    // phase 1: histogram + diagonal extraction
    for (int j = gt; j < tot; j += gs) {
        if (j < nnzN) {
            int r = nr[j], c = nc[j];
            if (r == c) atomicAdd(&g_dn[r], nv[j]);
            else atomicAdd(&g_cnt_n[r], 1);
        } else {
            int e = j - nnzN;
            int r = er[e], c = ec[e];
            if (r == c) atomicAdd(&g_de[r], ev[e]);
            else atomicAdd(&g_cnt_e[r], 1);
        }
    }
    gridbar();

    // phase 2: block-local scans (4096 elems/chunk), write local prefix + chunk sums
    __shared__ int sh[256];
    int nchunk = (N + 4095) / 4096;
    for (int chunk = blockIdx.x; chunk < 2 * nchunk; chunk += gridDim.x) {
        int edge = chunk >= nchunk;
        int cb = edge ? chunk - nchunk : chunk;
        const int* in = edge ? g_cnt_e : g_cnt_n;
        int* out = edge ? g_start_e : g_start_n;
        int* bsum = edge ? g_bsum_e : g_bsum_n;
        int base = cb * 4096 + tid * 16;
        int loc[16]; int s = 0;
#pragma unroll
        for (int k = 0; k < 16; k++) {
            loc[k] = (base + k < N) ? in[base + k] : 0;
            s += loc[k];
        }
        __syncthreads();
        sh[tid] = s; __syncthreads();
        for (int off = 1; off < 256; off <<= 1) {
            int t2 = (tid >= off) ? sh[tid - off] : 0;
            __syncthreads();
            sh[tid] += t2;
            __syncthreads();
        }
        int incl = sh[tid];
        int run = incl - s;
#pragma unroll
        for (int k = 0; k < 16; k++) {
            if (base + k < N) out[base + k] = run;
            run += loc[k];
        }
        if (tid == 255) bsum[cb] = incl;
    }
    gridbar();

    // phase 3: blocks 0/1 scan the chunk sums (exclusive)
    if (blockIdx.x < 2) {
        const int* bs = blockIdx.x ? g_bsum_e : g_bsum_n;
        int* bo = blockIdx.x ? g_boff_e : g_boff_n;
        int v = (tid < nchunk) ? bs[tid] : 0;
        __syncthreads();
        sh[tid] = v; __syncthreads();
        for (int off = 1; off < 256; off <<= 1) {
            int t2 = (tid >= off) ? sh[tid - off] : 0;
            __syncthreads();
            sh[tid] += t2;
            __syncthreads();
        }
        if (tid < nchunk) bo[tid] = sh[tid] - v;
    }
    gridbar();

    // phase 4: add chunk offsets
    for (int j = gt; j < N; j += gs) {
        g_start_n[j] += g_boff_n[j >> 12];
        g_start_e[j] += g_boff_e[j >> 12];
    }
    gridbar();

    // phase 5: scatter packed (col,val), filtered by dn/de
    for (int j = gt; j < tot; j += gs) {
        if (j < nnzN) {
            int r = nr[j], c = nc[j];
            if (r != c && g_dn[r] != 0.f) {
                int p = g_start_n[r] + atomicAdd(&g_cur_n[r], 1);
                g_pkn[p] = make_int2(c, __float_as_int(nv[j]));
            }
        } else {
            int e = j - nnzN;
            int r = er[e], c = ec[e];
            if (r != c && g_de[r] != 0.f) {
                int p = g_start_e[r] + atomicAdd(&g_cur_e[r], 1);
                g_pke[p] = make_int2(c, __float_as_int(ev[e]));
            }
        }
    }
}

// ============ K2: mlp — lin1, stats, lin2 fused (persistent) ============
__global__ void __launch_bounds__(256) k_mlp(
    const float* __restrict__ x,
    const float* __restrict__ W1, const float* __restrict__ b1,
    const float* __restrict__ gamma, const float* __restrict__ beta,
    const float* __restrict__ W2, const float* __restrict__ b2,
    int Nx, int Nold) {
    __shared__ float sW1[4096], sW2[4096];
    __shared__ float sB1[64], sB2[64];
    __shared__ float sScale[64], sShift[64];
    __shared__ float sS[64], sQ[64];
    int tid = threadIdx.x;
    int gt = blockIdx.x * 256 + tid;
    int gs = gridDim.x * 256;
    for (int t = tid; t < 4096; t += 256) { sW1[t] = W1[t]; sW2[t] = W2[t]; }
    if (tid < 64) {
        sB1[tid] = b1[tid]; sB2[tid] = b2[tid];
        sS[tid] = 0.f; sQ[tid] = 0.f;
    }
    __syncthreads();

    // phase 1: lin1 (thread-per-row)
    for (int i = gt; i < Nx; i += gs) {
        u64 x2[32];
        const ulonglong2* xr = reinterpret_cast<const ulonglong2*>(x + (size_t)i * NHID);
#pragma unroll
        for (int k = 0; k < 16; k++) { ulonglong2 v = xr[k]; x2[2*k] = v.x; x2[2*k+1] = v.y; }
        float4* o = reinterpret_cast<float4*>(g_t + (size_t)i * NHID);
        for (int jg = 0; jg < 16; jg++) {
            float res[4];
#pragma unroll
            for (int jj = 0; jj < 4; jj++) {
                int j = jg * 4 + jj;
                u64 acc = pack2(sB1[j], 0.f);
                const ulonglong2* wr = reinterpret_cast<const ulonglong2*>(sW1 + j * 64);
#pragma unroll
                for (int k = 0; k < 16; k++) {
                    ulonglong2 wv = wr[k];
                    fma2(acc, x2[2*k], wv.x);
                    fma2(acc, x2[2*k+1], wv.y);
                }
                float2 p = unpack2(acc);
                res[jj] = p.x + p.y;
            }
            o[jg] = make_float4(res[0], res[1], res[2], res[3]);
        }
    }
    gridbar();

    // phase 2: column stats over g_t
    {
        int cc = tid & 15;
        float4 s = make_float4(0.f,0.f,0.f,0.f), q = make_float4(0.f,0.f,0.f,0.f);
        for (int r = blockIdx.x * 16 + (tid >> 4); r < Nx; r += gridDim.x * 16) {
            float4 v = reinterpret_cast<const float4*>(g_t)[(size_t)r * 16 + cc];
            s.x += v.x; s.y += v.y; s.z += v.z; s.w += v.w;
            q.x += v.x*v.x; q.y += v.y*v.y; q.z += v.z*v.z; q.w += v.w*v.w;
        }
        int c0 = cc * 4;
        atomicAdd(&sS[c0], s.x);   atomicAdd(&sS[c0+1], s.y);
        atomicAdd(&sS[c0+2], s.z); atomicAdd(&sS[c0+3], s.w);
        atomicAdd(&sQ[c0], q.x);   atomicAdd(&sQ[c0+1], q.y);
        atomicAdd(&sQ[c0+2], q.z); atomicAdd(&sQ[c0+3], q.w);
        __syncthreads();
        if (tid < 64) {
            atomicAdd(&g_sum[tid], (double)sS[tid]);
            atomicAdd(&g_sumsq[tid], (double)sQ[tid]);
        }
    }
    gridbar();

    // phase 3: BN scale/shift then lin2 + h_update
    if (tid < 64) {
        double mu = g_sum[tid] / (double)Nx;
        double var = g_sumsq[tid] / (double)Nx - mu * mu;
        float inv = rsqrtf((float)var + BN_EPS);
        float sc = gamma[tid] * inv;
        sScale[tid] = sc;
        sShift[tid] = beta[tid] - (float)mu * sc;
    }
    __syncthreads();
    for (int i = gt; i < Nx; i += gs) {
        u64 x2[32];
        const float4* tr = reinterpret_cast<const float4*>(g_t + (size_t)i * NHID);
#pragma unroll
        for (int k = 0; k < 16; k++) {
            float4 v = tr[k];
            int k0 = k * 4;
            v.x = fmaxf(v.x * sScale[k0]   + sShift[k0],   0.f);
            v.y = fmaxf(v.y * sScale[k0+1] + sShift[k0+1], 0.f);
            v.z = fmaxf(v.z * sScale[k0+2] + sShift[k0+2], 0.f);
            v.w = fmaxf(v.w * sScale[k0+3] + sShift[k0+3], 0.f);
            x2[2*k] = pack2(v.x, v.y);
            x2[2*k+1] = pack2(v.z, v.w);
        }
        float dn = g_dn[Nold + i];
        float4* o = reinterpret_cast<float4*>(g_h + (size_t)(Nold + i) * NHID);
        for (int jg = 0; jg < 16; jg++) {
            float res[4];
#pragma unroll
            for (int jj = 0; jj < 4; jj++) {
                int j = jg * 4 + jj;
                u64 acc = pack2(sB2[j], 0.f);
                const ulonglong2* wr = reinterpret_cast<const ulonglong2*>(sW2 + j * 64);
#pragma unroll
                for (int k = 0; k < 16; k++) {
                    ulonglong2 wv = wr[k];
                    fma2(acc, x2[2*k], wv.x);
                    fma2(acc, x2[2*k+1], wv.y);
                }
                float2 p = unpack2(acc);
                res[jj] = (p.x + p.y) * dn;
            }
            o[jg] = make_float4(res[0], res[1], res[2], res[3]);
        }
    }
}

// ============ K3: spmm (R7 form: warp/row, 16-lane float4, 2 entries) ====
__global__ void k_spmm_csr(int N) {
    int w = (blockIdx.x * blockDim.x + threadIdx.x) >> 5;
    int lane = threadIdx.x & 31;
    if (w >= 2 * N) return;
    bool node = w < N;
    int r = node ? w : w - N;
    float scale = node ? g_dn[r] : g_de[r];
    if (scale == 0.f) return;
    const int2* pk = node ? g_pkn : g_pke;
    int s = node ? g_start_n[r] : g_start_e[r];
    int cnt = node ? g_cur_n[r] : g_cur_e[r];
    int half = lane >> 4, l16 = lane & 15;
    float4 acc = make_float4(0.f, 0.f, 0.f, 0.f);
    int p = s, e = s + cnt;
    for (; p + 4 <= e; p += 4) {
        int2 ea = pk[p + half];
        int2 eb = pk[p + 2 + half];
        float4 ha = reinterpret_cast<const float4*>(g_h + (size_t)ea.x * NHID)[l16];
        float4 hb = reinterpret_cast<const float4*>(g_h + (size_t)eb.x * NHID)[l16];
        float va = __int_as_float(ea.y), vb = __int_as_float(eb.y);
        acc.x += va * ha.x + vb * hb.x;
        acc.y += va * ha.y + vb * hb.y;
        acc.z += va * ha.z + vb * hb.z;
        acc.w += va * ha.w + vb * hb.w;
    }
    if (p + 2 <= e) {
        int2 ea = pk[p + half];
        float4 ha = reinterpret_cast<const float4*>(g_h + (size_t)ea.x * NHID)[l16];
        float va = __int_as_float(ea.y);
        acc.x += va * ha.x; acc.y += va * ha.y;
        acc.z += va * ha.z; acc.w += va * ha.w;
        p += 2;
    }
    if (p < e && half == 0) {
        int2 ea = pk[p];
        float4 ha = reinterpret_cast<const float4*>(g_h + (size_t)ea.x * NHID)[l16];
        float va = __int_as_float(ea.y);
        acc.x += va * ha.x; acc.y += va * ha.y;
        acc.z += va * ha.z; acc.w += va * ha.w;
    }
    acc.x += __shfl_xor_sync(0xffffffffu, acc.x, 16);
    acc.y += __shfl_xor_sync(0xffffffffu, acc.y, 16);
    acc.z += __shfl_xor_sync(0xffffffffu, acc.z, 16);
    acc.w += __shfl_xor_sync(0xffffffffu, acc.w, 16);
    if (half == 0) {
        float* M = node ? g_mn : g_me;
        reinterpret_cast<float4*>(M + (size_t)r * NHID)[l16] = acc;
    }
}

// ============ K4: persistent dual-weight GRU + heads =====================
#define SMG_BIAS 49152
#define SMG_WON  (SMG_BIAS + 768)
#define SMG_WOE  (SMG_WON + 64)
#define SMG_TOT  (SMG_WOE + 64)

__global__ void __launch_bounds__(256) k_gru(
    const float* __restrict__ Wi_n, const float* __restrict__ bi_n,
    const float* __restrict__ Wh_n, const float* __restrict__ bh_n,
    const float* __restrict__ Wi_e, const float* __restrict__ bi_e,
    const float* __restrict__ Wh_e, const float* __restrict__ bh_e,
    const float* __restrict__ w_on, const float* __restrict__ b_on,
    const float* __restrict__ w_oe, const float* __restrict__ b_oe,
    int N, float* __restrict__ out) {
    extern __shared__ float sm[];
    int tid = threadIdx.x;
    {
        float4* s4 = reinterpret_cast<float4*>(sm);
        const float4* a0 = reinterpret_cast<const float4*>(Wi_n);
        const float4* a1 = reinterpret_cast<const float4*>(Wh_n);
        const float4* a2 = reinterpret_cast<const float4*>(Wi_e);
        const float4* a3 = reinterpret_cast<const float4*>(Wh_e);
        for (int t = tid; t < 3072; t += 256) {
            s4[t] = a0[t];
            s4[3072 + t] = a1[t];
            s4[6144 + t] = a2[t];
            s4[9216 + t] = a3[t];
        }
        if (tid < 192) {
            sm[SMG_BIAS + tid] = bi_n[tid];
            sm[SMG_BIAS + 192 + tid] = bh_n[tid];
            sm[SMG_BIAS + 384 + tid] = bi_e[tid];
            sm[SMG_BIAS + 576 + tid] = bh_e[tid];
        }
        if (tid < 64) {
            sm[SMG_WON + tid] = w_on[tid];
            sm[SMG_WOE + tid] = w_oe[tid];
        }
    }
    __syncthreads();

    int wid = tid >> 5, lane = tid & 31;
    bool isNode = wid < 4;
    int local = isNode ? 2 * (wid * 32 + lane) : 2 * ((wid - 4) * 32 + lane) + 1;
    const float* mptr = isNode ? g_mn : g_me;
    const float* optr = isNode ? g_me : g_mn;
    const float* sWi = sm + (isNode ? 0 : 24576);
    const float* sWh = sWi + 12288;
    const float* sBi = sm + SMG_BIAS + (isNode ? 0 : 384);
    const float* sBh = sBi + 192;
    const float* gWi = isNode ? Wi_e : Wi_n;
    const float* gWh = isNode ? Wh_e : Wh_n;
    const float* gBi = isNode ? bi_e : bi_n;
    const float* gBh = isNode ? bh_e : bh_n;
    const float* sWon = sm + SMG_WON;
    const float* sWoe = sm + SMG_WOE;
    float* out_h = out + 2 * (size_t)N;
    float bon = b_on[0], boe = b_oe[0];

    u64 m2[32], h2[32];
    float hl[64];

    for (int base = blockIdx.x * 256; base < N; base += gridDim.x * 256) {
        int i = base + local;
        bool active = i < N;

        float dn_i = 0.f, de_i = 0.f;
        if (active) { dn_i = g_dn[i]; de_i = g_de[i]; }
        float scale  = isNode ? dn_i : de_i;
        float oscale = isNode ? de_i : dn_i;

        if (active) {
            const float4* h4 = reinterpret_cast<const float4*>(g_h + (size_t)i * NHID);
#pragma unroll
            for (int k = 0; k < 16; k++) {
                float4 a = h4[k];
                hl[4*k] = a.x; hl[4*k+1] = a.y; hl[4*k+2] = a.z; hl[4*k+3] = a.w;
                h2[2*k] = pack2(a.x, a.y);
                h2[2*k+1] = pack2(a.z, a.w);
            }
        }
        float s_on = 0.f, s_oe = 0.f;

        bool did_main = active && (scale != 0.f);
        if (did_main) {
            const ulonglong2* mm = reinterpret_cast<const ulonglong2*>(mptr + (size_t)i * NHID);
#pragma unroll
            for (int k = 0; k < 16; k++) {
                ulonglong2 mv = mm[k];
                m2[2*k] = mv.x; m2[2*k+1] = mv.y;
            }
            for (int jp = 0; jp < 32; jp++) {
                int j0 = 2 * jp, j1 = 2 * jp + 1;
                u64 aR0 = pack2(sBi[j0], 0.f),      aR1 = pack2(sBi[j1], 0.f);
                u64 aZ0 = pack2(sBi[64 + j0], 0.f),  aZ1 = pack2(sBi[64 + j1], 0.f);
                u64 aN0 = pack2(sBi[128 + j0], 0.f), aN1 = pack2(sBi[128 + j1], 0.f);
                u64 bR0 = pack2(sBh[j0], 0.f),      bR1 = pack2(sBh[j1], 0.f);
                u64 bZ0 = pack2(sBh[64 + j0], 0.f),  bZ1 = pack2(sBh[64 + j1], 0.f);
                u64 bN0 = pack2(sBh[128 + j0], 0.f), bN1 = pack2(sBh[128 + j1], 0.f);
                const ulonglong2* w0 = reinterpret_cast<const ulonglong2*>(sWi + j0 * 64);
                const ulonglong2* w1 = reinterpret_cast<const ulonglong2*>(sWi + (64 + j0) * 64);
                const ulonglong2* w2 = reinterpret_cast<const ulonglong2*>(sWi + (128 + j0) * 64);
                const ulonglong2* v0 = reinterpret_cast<const ulonglong2*>(sWh + j0 * 64);
                const ulonglong2* v1 = reinterpret_cast<const ulonglong2*>(sWh + (64 + j0) * 64);
                const ulonglong2* v2 = reinterpret_cast<const ulonglong2*>(sWh + (128 + j0) * 64);
#pragma unroll
                for (int kk = 0; kk < 16; kk++) {
                    u64 ma = m2[2*kk], mb = m2[2*kk+1];
                    u64 ha = h2[2*kk], hb = h2[2*kk+1];
                    ulonglong2 W0a = w0[kk], W0b = w0[kk + 16];
                    ulonglong2 W1a = w1[kk], W1b = w1[kk + 16];
                    ulonglong2 W2a = w2[kk], W2b = w2[kk + 16];
                    ulonglong2 V0a = v0[kk], V0b = v0[kk + 16];
                    ulonglong2 V1a = v1[kk], V1b = v1[kk + 16];
                    ulonglong2 V2a = v2[kk], V2b = v2[kk + 16];
                    fma2(aR0, ma, W0a.x); fma2(aR0, mb, W0a.y);
                    fma2(aR1, ma, W0b.x); fma2(aR1, mb, W0b.y);
                    fma2(aZ0, ma, W1a.x); fma2(aZ0, mb, W1a.y);
                    fma2(aZ1, ma, W1b.x); fma2(aZ1, mb, W1b.y);
                    fma2(aN0, ma, W2a.x); fma2(aN0, mb, W2a.y);
                    fma2(aN1, ma, W2b.x); fma2(aN1, mb, W2b.y);
                    fma2(bR0, ha, V0a.x); fma2(bR0, hb, V0a.y);
                    fma2(bR1, ha, V0b.x); fma2(bR1, hb, V0b.y);
                    fma2(bZ0, ha, V1a.x); fma2(bZ0, hb, V1a.y);
                    fma2(bZ1, ha, V1b.x); fma2(bZ1, hb, V1b.y);
                    fma2(bN0, ha, V2a.x); fma2(bN0, hb, V2a.y);
                    fma2(bN1, ha, V2b.x); fma2(bN1, hb, V2b.y);
                }
                float2 t;
                t = unpack2(aR0); float pr0 = t.x + t.y;
                t = unpack2(aR1); float pr1 = t.x + t.y;
                t = unpack2(aZ0); float pz0 = t.x + t.y;
                t = unpack2(aZ1); float pz1 = t.x + t.y;
                t = unpack2(aN0); float pn0 = t.x + t.y;
                t = unpack2(aN1); float pn1 = t.x + t.y;
                t = unpack2(bR0); float qr0 = t.x + t.y;
                t = unpack2(bR1); float qr1 = t.x + t.y;
                t = unpack2(bZ0); float qz0 = t.x + t.y;
                t = unpack2(bZ1); float qz1 = t.x + t.y;
                t = unpack2(bN0); float qn0 = t.x + t.y;
                t = unpack2(bN1); float qn1 = t.x + t.y;
                float r0 = sigmf(pr0 + qr0), r1 = sigmf(pr1 + qr1);
                float z0 = sigmf(pz0 + qz0), z1 = sigmf(pz1 + qz1);
                float ng0 = tanhfast(pn0 + r0 * qn0), ng1 = tanhfast(pn1 + r1 * qn1);
                float hf0 = scale * ((1.f - z0) * ng0 + z0 * hl[j0]);
                float hf1 = scale * ((1.f - z1) * ng1 + z1 * hl[j1]);
                reinterpret_cast<float2*>(out_h + (size_t)i * NHID)[jp] = make_float2(hf0, hf1);
                s_on += hf0 * sWon[j0] + hf1 * sWon[j1];
                s_oe += hf0 * sWoe[j0] + hf1 * sWoe[j1];
            }
        } else if (active) {
            float4 z4 = make_float4(0.f, 0.f, 0.f, 0.f);
            float4* o4 = reinterpret_cast<float4*>(out_h + (size_t)i * NHID);
#pragma unroll
            for (int k = 0; k < 16; k++) o4[k] = z4;
        }

        bool need2 = active && (oscale != 0.f);
        if (need2) {
            s_on = 0.f; s_oe = 0.f;
            const float* mo = optr + (size_t)i * NHID;
            float ml[64];
#pragma unroll
            for (int k = 0; k < 64; k++) ml[k] = mo[k];
            for (int j = 0; j < NHID; j++) {
                float ir = gBi[j], iz = gBi[64 + j], in_ = gBi[128 + j];
                float hr = gBh[j], hz = gBh[64 + j], hn = gBh[128 + j];
                for (int k = 0; k < 64; k++) {
                    ir += ml[k] * gWi[j * 64 + k];
                    iz += ml[k] * gWi[(64 + j) * 64 + k];
                    in_ += ml[k] * gWi[(128 + j) * 64 + k];
                    hr += hl[k] * gWh[j * 64 + k];
                    hz += hl[k] * gWh[(64 + j) * 64 + k];
                    hn += hl[k] * gWh[(128 + j) * 64 + k];
                }
                float r = sigmf(ir + hr);
                float z = sigmf(iz + hz);
                float ng = tanhfast(in_ + r * hn);
                float hv = (1.f - z) * ng + z * hl[j];
                size_t oi = (size_t)i * NHID + j;
                float hf = out_h[oi] + oscale * hv;
                out_h[oi] = hf;
                s_on += hf * sWon[j];
                s_oe += hf * sWoe[j];
            }
        }

        if (active) {
            float y = dn_i * (s_on + bon) + de_i * (s_oe + boe);
            out[i] = sigmf(y);
            out[(size_t)N + i] = y;
        }
    }
}

// ---------------- launch ----------------
extern "C" void kernel_launch(void* const* d_in, const int* in_sizes, int n_in,
                              void* d_out, int out_size) {
    const float* x     = (const float*)d_in[0];
    const float* h_in  = (const float*)d_in[1];
    const int*   nr    = (const int*)d_in[2];
    const int*   nc    = (const int*)d_in[3];
    const float* nv    = (const float*)d_in[4];
    const int*   er    = (const int*)d_in[5];
    const int*   ec    = (const int*)d_in[6];
    const float* ev    = (const float*)d_in[7];
    const float* W1    = (const float*)d_in[8];
    const float* b1    = (const float*)d_in[9];
    const float* gamma = (const float*)d_in[10];
    const float* beta  = (const float*)d_in[11];
    const float* W2    = (const float*)d_in[12];
    const float* b2    = (const float*)d_in[13];
    const float* Wi_n  = (const float*)d_in[14];
    const float* bi_n  = (const float*)d_in[15];
    const float* Wh_n  = (const float*)d_in[16];
    const float* bh_n  = (const float*)d_in[17];
    const float* Wi_e  = (const float*)d_in[18];
    const float* bi_e  = (const float*)d_in[19];
    const float* Wh_e  = (const float*)d_in[20];
    const float* bh_e  = (const float*)d_in[21];
    const float* w_on  = (const float*)d_in[22];
    const float* b_on  = (const float*)d_in[23];
    const float* w_oe  = (const float*)d_in[24];
    const float* b_oe  = (const float*)d_in[25];

    int Nx   = in_sizes[0] / NHID;
    int Nold = in_sizes[1] / NHID;
    int N    = Nx + Nold;
    int nnzN = in_sizes[2];
    int nnzE = in_sizes[5];
    float* out = (float*)d_out;

    int dev = 0, nsm = 148;
    cudaGetDevice(&dev);
    cudaDeviceGetAttribute(&nsm, cudaDevAttrMultiProcessorCount, dev);

    cudaFuncSetAttribute(k_gru, cudaFuncAttributeMaxDynamicSharedMemorySize,
                         SMG_TOT * sizeof(float));

    k_build<<<nsm, 256>>>((const float4*)h_in,                          // 1
                          nr, nc, nv, nnzN, er, ec, ev, nnzE, N, Nold);
    k_mlp<<<nsm, 256>>>(x, W1, b1, gamma, beta, W2, b2, Nx, Nold);      // 2
    {
        long long warps = 2LL * N;
        int blocks = (int)((warps * 32 + 255) / 256);
        k_spmm_csr<<<blocks, 256>>>(N);                                 // 3
    }
    k_gru<<<nsm, 256, SMG_TOT * sizeof(float)>>>(                       // 4 (profiled)
        Wi_n, bi_n, Wh_n, bh_n, Wi_e, bi_e, Wh_e, bh_e,
        w_on, b_on, w_oe, b_oe, N, out);
}

// round 10
// speedup vs baseline: 1.1865x; 1.1865x over previous
#include <cuda_runtime.h>
#include <math.h>

#define NHID 64
#define NMAX 400000
#define NXMAX 100000
#define NNZCAP 2200000
#define BN_EPS 1e-5f
#define NSM 148

typedef unsigned long long u64;

// ---------------- scratch (device globals; no allocations) ----------------
__device__ __align__(256) float  g_dn[NMAX];
__device__ __align__(256) float  g_de[NMAX];
__device__ __align__(256) float  g_h [NMAX * NHID];
__device__ __align__(256) float  g_mn[NMAX * NHID];
__device__ __align__(256) float  g_me[NMAX * NHID];
__device__ __align__(256) float  g_t [NXMAX * NHID];
__device__ double g_sum[NHID];
__device__ double g_sumsq[NHID];
__device__ __align__(256) int   g_cnt_n[NMAX], g_cnt_e[NMAX];
__device__ __align__(256) int   g_cur_n[NMAX], g_cur_e[NMAX];
__device__ __align__(256) int   g_start_n[NMAX], g_start_e[NMAX];
__device__ __align__(256) int2  g_pkn[NNZCAP], g_pke[NNZCAP];
__device__ int g_bsum_n[4096], g_bsum_e[4096], g_boff_n[4096], g_boff_e[4096];

// ---------------- helpers ----------------
__device__ __forceinline__ u64 pack2(float lo, float hi) {
    u64 r; asm("mov.b64 %0, {%1,%2};" : "=l"(r) : "f"(lo), "f"(hi)); return r;
}
__device__ __forceinline__ float2 unpack2(u64 v) {
    float2 r; asm("mov.b64 {%0,%1}, %2;" : "=f"(r.x), "=f"(r.y) : "l"(v)); return r;
}
__device__ __forceinline__ void fma2(u64& acc, u64 a, u64 b) {
    asm("fma.rn.f32x2 %0, %1, %2, %0;" : "+l"(acc) : "l"(a), "l"(b));
}
__device__ __forceinline__ float sigmf(float x) {
    return __fdividef(1.0f, 1.0f + __expf(-x));
}
__device__ __forceinline__ float tanhfast(float x) {
    return 2.0f * sigmf(2.0f * x) - 1.0f;
}

// ---------------- K0: zero scratch + copy h_in (merged) ----------------
__global__ void k_init(const float4* __restrict__ h_src, int n4, int N) {
    int i = blockIdx.x * blockDim.x + threadIdx.x;
    int stride = gridDim.x * blockDim.x;
    float4* dst = reinterpret_cast<float4*>(g_h);
    for (int j = i; j < n4; j += stride) dst[j] = h_src[j];
    for (int j = i; j < N; j += stride) {
        g_dn[j] = 0.f; g_de[j] = 0.f;
        g_cnt_n[j] = 0; g_cnt_e[j] = 0;
        g_cur_n[j] = 0; g_cur_e[j] = 0;
    }
    if (i < NHID) { g_sum[i] = 0.0; g_sumsq[i] = 0.0; }
}

// ---------------- K1: histogram + diagonal extraction ----------------
__global__ void k_hist(const int* __restrict__ nr, const int* __restrict__ nc,
                       const float* __restrict__ nv, int nnzN,
                       const int* __restrict__ er, const int* __restrict__ ec,
                       const float* __restrict__ ev, int nnzE) {
    int j = blockIdx.x * blockDim.x + threadIdx.x;
    int tot = nnzN + nnzE;
    if (j >= tot) return;
    if (j < nnzN) {
        int r = nr[j], c = nc[j];
        if (r == c) atomicAdd(&g_dn[r], nv[j]);
        else atomicAdd(&g_cnt_n[r], 1);
    } else {
        int e = j - nnzN;
        int r = er[e], c = ec[e];
        if (r == c) atomicAdd(&g_de[r], ev[e]);
        else atomicAdd(&g_cnt_e[r], 1);
    }
}

// ---------------- scans (blockIdx.y: 0=node, 1=edge) ----------------
__global__ void k_scan1(int n) {
    int edge = blockIdx.y;
    const int* in = edge ? g_cnt_e : g_cnt_n;
    int* out = edge ? g_start_e : g_start_n;
    int* bsum = edge ? g_bsum_e : g_bsum_n;
    __shared__ int sh[256];
    int tid = threadIdx.x;
    int base = blockIdx.x * 4096 + tid * 16;
    int loc[16]; int s = 0;
#pragma unroll
    for (int k = 0; k < 16; k++) {
        loc[k] = (base + k < n) ? in[base + k] : 0;
        s += loc[k];
    }
    sh[tid] = s; __syncthreads();
    for (int off = 1; off < 256; off <<= 1) {
        int t2 = (tid >= off) ? sh[tid - off] : 0;
        __syncthreads();
        sh[tid] += t2;
        __syncthreads();
    }
    int incl = sh[tid];
    int run = incl - s;
#pragma unroll
    for (int k = 0; k < 16; k++) {
        if (base + k < n) out[base + k] = run;
        run += loc[k];
    }
    if (tid == 255) bsum[blockIdx.x] = incl;
}

__global__ void k_scan2(int nblk) {
    int edge = blockIdx.x;
    const int* bsum = edge ? g_bsum_e : g_bsum_n;
    int* boff = edge ? g_boff_e : g_boff_n;
    __shared__ int sh[256];
    int tid = threadIdx.x;
    int base = tid * 16;
    int loc[16]; int s = 0;
#pragma unroll
    for (int k = 0; k < 16; k++) {
        loc[k] = (base + k < nblk) ? bsum[base + k] : 0;
        s += loc[k];
    }
    sh[tid] = s; __syncthreads();
    for (int off = 1; off < 256; off <<= 1) {
        int t2 = (tid >= off) ? sh[tid - off] : 0;
        __syncthreads();
        sh[tid] += t2;
        __syncthreads();
    }
    int incl = sh[tid];
    int run = incl - s;
#pragma unroll
    for (int k = 0; k < 16; k++) {
        if (base + k < nblk) boff[base + k] = run;
        run += loc[k];
    }
}

__global__ void k_scan3(int n) {
    int edge = blockIdx.y;
    int* out = edge ? g_start_e : g_start_n;
    const int* boff = edge ? g_boff_e : g_boff_n;
    int i = blockIdx.x * blockDim.x + threadIdx.x;
    int stride = gridDim.x * blockDim.x;
    for (int j = i; j < n; j += stride) out[j] += boff[j >> 12];
}

// ---------------- K-scatter: build packed CSR, filtered ----------------
__global__ void k_scatter(const int* __restrict__ nr, const int* __restrict__ nc,
                          const float* __restrict__ nv, int nnzN,
                          const int* __restrict__ er, const int* __restrict__ ec,
                          const float* __restrict__ ev, int nnzE) {
    int j = blockIdx.x * blockDim.x + threadIdx.x;
    int tot = nnzN + nnzE;
    if (j >= tot) return;
    if (j < nnzN) {
        int r = nr[j], c = nc[j];
        if (r != c && g_dn[r] != 0.f) {
            int p = g_start_n[r] + atomicAdd(&g_cur_n[r], 1);
            g_pkn[p] = make_int2(c, __float_as_int(nv[j]));
        }
    } else {
        int e = j - nnzN;
        int r = er[e], c = ec[e];
        if (r != c && g_de[r] != 0.f) {
            int p = g_start_e[r] + atomicAdd(&g_cur_e[r], 1);
            g_pke[p] = make_int2(c, __float_as_int(ev[e]));
        }
    }
}

// ---------------- K-spmm CSR: warp per row, 16-lane float4, 2 entries --
__global__ void k_spmm_csr(int N) {
    int w = (blockIdx.x * blockDim.x + threadIdx.x) >> 5;
    int lane = threadIdx.x & 31;
    if (w >= 2 * N) return;
    bool node = w < N;
    int r = node ? w : w - N;
    float scale = node ? g_dn[r] : g_de[r];
    if (scale == 0.f) return;
    const int2* pk = node ? g_pkn : g_pke;
    int s = node ? g_start_n[r] : g_start_e[r];
    int cnt = node ? g_cur_n[r] : g_cur_e[r];
    int half = lane >> 4, l16 = lane & 15;
    float4 acc = make_float4(0.f, 0.f, 0.f, 0.f);
    int p = s, e = s + cnt;
    for (; p + 4 <= e; p += 4) {
        int2 ea = pk[p + half];
        int2 eb = pk[p + 2 + half];
        float4 ha = reinterpret_cast<const float4*>(g_h + (size_t)ea.x * NHID)[l16];
        float4 hb = reinterpret_cast<const float4*>(g_h + (size_t)eb.x * NHID)[l16];
        float va = __int_as_float(ea.y), vb = __int_as_float(eb.y);
        acc.x += va * ha.x + vb * hb.x;
        acc.y += va * ha.y + vb * hb.y;
        acc.z += va * ha.z + vb * hb.z;
        acc.w += va * ha.w + vb * hb.w;
    }
    if (p + 2 <= e) {
        int2 ea = pk[p + half];
        float4 ha = reinterpret_cast<const float4*>(g_h + (size_t)ea.x * NHID)[l16];
        float va = __int_as_float(ea.y);
        acc.x += va * ha.x; acc.y += va * ha.y;
        acc.z += va * ha.z; acc.w += va * ha.w;
        p += 2;
    }
    if (p < e && half == 0) {
        int2 ea = pk[p];
        float4 ha = reinterpret_cast<const float4*>(g_h + (size_t)ea.x * NHID)[l16];
        float va = __int_as_float(ea.y);
        acc.x += va * ha.x; acc.y += va * ha.y;
        acc.z += va * ha.z; acc.w += va * ha.w;
    }
    acc.x += __shfl_xor_sync(0xffffffffu, acc.x, 16);
    acc.y += __shfl_xor_sync(0xffffffffu, acc.y, 16);
    acc.z += __shfl_xor_sync(0xffffffffu, acc.z, 16);
    acc.w += __shfl_xor_sync(0xffffffffu, acc.w, 16);
    if (half == 0) {
        float* M = node ? g_mn : g_me;
        reinterpret_cast<float4*>(M + (size_t)r * NHID)[l16] = acc;
    }
}

// ---------------- K3: lin1, thread-per-row ----------------
__global__ void __launch_bounds__(256) k_lin1(
    const float* __restrict__ x, const float* __restrict__ W1,
    const float* __restrict__ b1, int Nx) {
    __shared__ float sW[4096];
    __shared__ float sB[64];
    int tid = threadIdx.x;
    for (int t = tid; t < 4096; t += 256) sW[t] = W1[t];
    if (tid < 64) sB[tid] = b1[tid];
    __syncthreads();
    int i = blockIdx.x * 256 + tid;
    if (i >= Nx) return;
    u64 x2[32];
    const ulonglong2* xr = reinterpret_cast<const ulonglong2*>(x + (size_t)i * NHID);
#pragma unroll
    for (int k = 0; k < 16; k++) { ulonglong2 v = xr[k]; x2[2 * k] = v.x; x2[2 * k + 1] = v.y; }
    float4* o = reinterpret_cast<float4*>(g_t + (size_t)i * NHID);
    for (int jg = 0; jg < 16; jg++) {
        float res[4];
#pragma unroll
        for (int jj = 0; jj < 4; jj++) {
            int j = jg * 4 + jj;
            u64 acc = pack2(sB[j], 0.f);
            const ulonglong2* wr = reinterpret_cast<const ulonglong2*>(sW + j * 64);
#pragma unroll
            for (int k = 0; k < 16; k++) {
                ulonglong2 wv = wr[k];
                fma2(acc, x2[2 * k], wv.x);
                fma2(acc, x2[2 * k + 1], wv.y);
            }
            float2 p = unpack2(acc);
            res[jj] = p.x + p.y;
        }
        o[jg] = make_float4(res[0], res[1], res[2], res[3]);
    }
}

// ---------------- K-stats ----------------
__global__ void k_stats(int Nx) {
    __shared__ float sS[64], sQ[64];
    int tid = threadIdx.x;
    if (tid < 64) { sS[tid] = 0.f; sQ[tid] = 0.f; }
    __syncthreads();
    int cc = tid & 15;
    float4 s = make_float4(0.f, 0.f, 0.f, 0.f);
    float4 q = make_float4(0.f, 0.f, 0.f, 0.f);
    for (int r = blockIdx.x * 16 + (tid >> 4); r < Nx; r += gridDim.x * 16) {
        float4 v = reinterpret_cast<const float4*>(g_t)[(size_t)r * 16 + cc];
        s.x += v.x; s.y += v.y; s.z += v.z; s.w += v.w;
        q.x += v.x * v.x; q.y += v.y * v.y; q.z += v.z * v.z; q.w += v.w * v.w;
    }
    int c0 = cc * 4;
    atomicAdd(&sS[c0], s.x); atomicAdd(&sS[c0 + 1], s.y);
    atomicAdd(&sS[c0 + 2], s.z); atomicAdd(&sS[c0 + 3], s.w);
    atomicAdd(&sQ[c0], q.x); atomicAdd(&sQ[c0 + 1], q.y);
    atomicAdd(&sQ[c0 + 2], q.z); atomicAdd(&sQ[c0 + 3], q.w);
    __syncthreads();
    if (tid < 64) {
        atomicAdd(&g_sum[tid], (double)sS[tid]);
        atomicAdd(&g_sumsq[tid], (double)sQ[tid]);
    }
}

// ---------------- K4: BN + ReLU + lin2 + h_update ----------------
__global__ void __launch_bounds__(256) k_lin2(
    const float* __restrict__ gamma, const float* __restrict__ beta,
    const float* __restrict__ W2, const float* __restrict__ b2,
    int Nx, int Nold) {
    __shared__ float sW[4096];
    __shared__ float sB[64];
    __shared__ float sScale[64], sShift[64];
    int tid = threadIdx.x;
    for (int t = tid; t < 4096; t += 256) sW[t] = W2[t];
    if (tid < 64) {
        sB[tid] = b2[tid];
        double mu = g_sum[tid] / (double)Nx;
        double var = g_sumsq[tid] / (double)Nx - mu * mu;
        float inv = rsqrtf((float)var + BN_EPS);
        float sc = gamma[tid] * inv;
        sScale[tid] = sc;
        sShift[tid] = beta[tid] - (float)mu * sc;
    }
    __syncthreads();
    int i = blockIdx.x * 256 + tid;
    if (i >= Nx) return;
    u64 x2[32];
    const float4* tr = reinterpret_cast<const float4*>(g_t + (size_t)i * NHID);
#pragma unroll
    for (int k = 0; k < 16; k++) {
        float4 v = tr[k];
        int k0 = k * 4;
        v.x = fmaxf(v.x * sScale[k0] + sShift[k0], 0.f);
        v.y = fmaxf(v.y * sScale[k0 + 1] + sShift[k0 + 1], 0.f);
        v.z = fmaxf(v.z * sScale[k0 + 2] + sShift[k0 + 2], 0.f);
        v.w = fmaxf(v.w * sScale[k0 + 3] + sShift[k0 + 3], 0.f);
        x2[2 * k] = pack2(v.x, v.y);
        x2[2 * k + 1] = pack2(v.z, v.w);
    }
    float dn = g_dn[Nold + i];
    float4* o = reinterpret_cast<float4*>(g_h + (size_t)(Nold + i) * NHID);
    for (int jg = 0; jg < 16; jg++) {
        float res[4];
#pragma unroll
        for (int jj = 0; jj < 4; jj++) {
            int j = jg * 4 + jj;
            u64 acc = pack2(sB[j], 0.f);
            const ulonglong2* wr = reinterpret_cast<const ulonglong2*>(sW + j * 64);
#pragma unroll
            for (int k = 0; k < 16; k++) {
                ulonglong2 wv = wr[k];
                fma2(acc, x2[2 * k], wv.x);
                fma2(acc, x2[2 * k + 1], wv.y);
            }
            float2 p = unpack2(acc);
            res[jj] = (p.x + p.y) * dn;
        }
        o[jg] = make_float4(res[0], res[1], res[2], res[3]);
    }
}

// ---------------- K6: persistent GRU, k-split-2 x 2-rows/thread --------
// smem weight layout: 16B granule order (j, kk, kh):
//   float offset = j*64 + kk*8 + kh*4   (ulonglong2 index = j*16 + kk*2 + kh)
#define SMG_BIAS 49152
#define SMG_WON  (SMG_BIAS + 768)
#define SMG_WOE  (SMG_WON + 64)
#define SMG_TOT  (SMG_WOE + 64)

__global__ void __launch_bounds__(256) k_gru(
    const float* __restrict__ Wi_n, const float* __restrict__ bi_n,
    const float* __restrict__ Wh_n, const float* __restrict__ bh_n,
    const float* __restrict__ Wi_e, const float* __restrict__ bi_e,
    const float* __restrict__ Wh_e, const float* __restrict__ bh_e,
    const float* __restrict__ w_on, const float* __restrict__ b_on,
    const float* __restrict__ w_oe, const float* __restrict__ b_oe,
    int N, float* __restrict__ out) {
    extern __shared__ float sm[];
    int tid = threadIdx.x;
    {
        float4* s4 = reinterpret_cast<float4*>(sm);
        const float4* a0 = reinterpret_cast<const float4*>(Wi_n);
        const float4* a1 = reinterpret_cast<const float4*>(Wh_n);
        const float4* a2 = reinterpret_cast<const float4*>(Wi_e);
        const float4* a3 = reinterpret_cast<const float4*>(Wh_e);
        for (int t = tid; t < 3072; t += 256) {
            int j = t >> 4, w4 = t & 15;
            int kh = w4 >> 3, kk = w4 & 7;
            int d = j * 16 + kk * 2 + kh;
            s4[d] = a0[t];
            s4[3072 + d] = a1[t];
            s4[6144 + d] = a2[t];
            s4[9216 + d] = a3[t];
        }
        if (tid < 192) {
            sm[SMG_BIAS + tid] = bi_n[tid];
            sm[SMG_BIAS + 192 + tid] = bh_n[tid];
            sm[SMG_BIAS + 384 + tid] = bi_e[tid];
            sm[SMG_BIAS + 576 + tid] = bh_e[tid];
        }
        if (tid < 64) {
            sm[SMG_WON + tid] = w_on[tid];
            sm[SMG_WOE + tid] = w_oe[tid];
        }
    }
    __syncthreads();

    int wid = tid >> 5, lane = tid & 31;
    bool isNode = wid < 4;
    int kh = lane >> 4;       // k-half: 0 = dims 0..31, 1 = dims 32..63
    int l16 = lane & 15;
    int pairIdx = (isNode ? wid : wid - 4) * 16 + l16;  // 0..63
    int par = isNode ? 0 : 1;
    const float* mptr = isNode ? g_mn : g_me;
    const float* optr = isNode ? g_me : g_mn;
    const float* sWi = sm + (isNode ? 0 : 24576);
    const float* sWh = sWi + 12288;
    const float* sBi = sm + SMG_BIAS + (isNode ? 0 : 384);
    const float* sBh = sBi + 192;
    const float* gWi = isNode ? Wi_e : Wi_n;
    const float* gWh = isNode ? Wh_e : Wh_n;
    const float* gBi = isNode ? bi_e : bi_n;
    const float* gBh = isNode ? bh_e : bh_n;
    const float* sWon = sm + SMG_WON;
    const float* sWoe = sm + SMG_WOE;
    float* out_h = out + 2 * (size_t)N;
    float bon = b_on[0], boe = b_oe[0];

    u64 mA[16], hA[16], mB[16], hB[16];
    float hOwn[32], hOth[32];

    for (int base = blockIdx.x * 256; base < N; base += gridDim.x * 256) {
        int iA = base + 4 * pairIdx + par;
        int iB = iA + 2;
        bool actA = iA < N, actB = iB < N;

        float dnA = 0.f, deA = 0.f, dnB = 0.f, deB = 0.f;
        if (actA) { dnA = g_dn[iA]; deA = g_de[iA]; }
        if (actB) { dnB = g_dn[iB]; deB = g_de[iB]; }
        float scaleA = isNode ? dnA : deA;
        float scaleB = isNode ? dnB : deB;

        if (actA) {
            const ulonglong2* mm = reinterpret_cast<const ulonglong2*>(mptr + (size_t)iA * NHID + kh * 32);
            const ulonglong2* hh = reinterpret_cast<const ulonglong2*>(g_h + (size_t)iA * NHID + kh * 32);
#pragma unroll
            for (int k = 0; k < 8; k++) {
                ulonglong2 v = mm[k]; mA[2 * k] = v.x; mA[2 * k + 1] = v.y;
                ulonglong2 w = hh[k]; hA[2 * k] = w.x; hA[2 * k + 1] = w.y;
            }
        }
        if (actB) {
            const ulonglong2* mm = reinterpret_cast<const ulonglong2*>(mptr + (size_t)iB * NHID + kh * 32);
            const ulonglong2* hh = reinterpret_cast<const ulonglong2*>(g_h + (size_t)iB * NHID + kh * 32);
#pragma unroll
            for (int k = 0; k < 8; k++) {
                ulonglong2 v = mm[k]; mB[2 * k] = v.x; mB[2 * k + 1] = v.y;
                ulonglong2 w = hh[k]; hB[2 * k] = w.x; hB[2 * k + 1] = w.y;
            }
        }
        // epilogue ownership: kh0 -> row A, kh1 -> row B
#pragma unroll
        for (int k = 0; k < 16; k++) {
            float2 a = unpack2(hA[k]);
            float2 b = unpack2(hB[k]);
            if (kh == 0) {
                hOwn[2 * k] = a.x; hOwn[2 * k + 1] = a.y;
                hOth[2 * k] = b.x; hOth[2 * k + 1] = b.y;
            } else {
                hOwn[2 * k] = b.x; hOwn[2 * k + 1] = b.y;
                hOth[2 * k] = a.x; hOth[2 * k + 1] = a.y;
            }
        }

        int iE = kh ? iB : iA;
        bool actE = kh ? actB : actA;
        float scaleE = kh ? scaleB : scaleA;
        float dnE = kh ? dnB : dnA;
        float deE = kh ? deB : deA;
        float oscaleE = isNode ? deE : dnE;

        float s_on = 0.f, s_oe = 0.f;
        float2 pairStore = make_float2(0.f, 0.f);

        for (int j = 0; j < 64; j++) {
            u64 aRA = 0, aZA = 0, aNA = 0, bRA = 0, bZA = 0, bNA = 0;
            u64 aRB = 0, aZB = 0, aNB = 0, bRB = 0, bZB = 0, bNB = 0;
            const ulonglong2* w0 = reinterpret_cast<const ulonglong2*>(sWi) + (j * 16 + kh);
            const ulonglong2* w1 = reinterpret_cast<const ulonglong2*>(sWi) + ((64 + j) * 16 + kh);
            const ulonglong2* w2 = reinterpret_cast<const ulonglong2*>(sWi) + ((128 + j) * 16 + kh);
            const ulonglong2* v0 = reinterpret_cast<const ulonglong2*>(sWh) + (j * 16 + kh);
            const ulonglong2* v1 = reinterpret_cast<const ulonglong2*>(sWh) + ((64 + j) * 16 + kh);
            const ulonglong2* v2 = reinterpret_cast<const ulonglong2*>(sWh) + ((128 + j) * 16 + kh);
#pragma unroll
            for (int kk = 0; kk < 8; kk++) {
                ulonglong2 W0 = w0[2 * kk], W1 = w1[2 * kk], W2 = w2[2 * kk];
                ulonglong2 V0 = v0[2 * kk], V1 = v1[2 * kk], V2 = v2[2 * kk];
                u64 ma = mA[2 * kk], mb = mA[2 * kk + 1];
                u64 na = mB[2 * kk], nb = mB[2 * kk + 1];
                u64 ha = hA[2 * kk], hb = hA[2 * kk + 1];
                u64 pa = hB[2 * kk], pb = hB[2 * kk + 1];
                fma2(aRA, ma, W0.x); fma2(aRA, mb, W0.y);
                fma2(aRB, na, W0.x); fma2(aRB, nb, W0.y);
                fma2(aZA, ma, W1.x); fma2(aZA, mb, W1.y);
                fma2(aZB, na, W1.x); fma2(aZB, nb, W1.y);
                fma2(aNA, ma, W2.x); fma2(aNA, mb, W2.y);
                fma2(aNB, na, W2.x); fma2(aNB, nb, W2.y);
                fma2(bRA, ha, V0.x); fma2(bRA, hb, V0.y);
                fma2(bRB, pa, V0.x); fma2(bRB, pb, V0.y);
                fma2(bZA, ha, V1.x); fma2(bZA, hb, V1.y);
                fma2(bZB, pa, V1.x); fma2(bZB, pb, V1.y);
                fma2(bNA, ha, V2.x); fma2(bNA, hb, V2.y);
                fma2(bNB, pa, V2.x); fma2(bNB, pb, V2.y);
            }
            // exchange other-row partials with partner (lane ^ 16)
            u64 sR = kh ? aRA : aRB;  u64 sZ = kh ? aZA : aZB;  u64 sN = kh ? aNA : aNB;
            u64 tR = kh ? bRA : bRB;  u64 tZ = kh ? bZA : bZB;  u64 tN = kh ? bNA : bNB;
            u64 rR = __shfl_xor_sync(0xffffffffu, sR, 16);
            u64 rZ = __shfl_xor_sync(0xffffffffu, sZ, 16);
            u64 rN = __shfl_xor_sync(0xffffffffu, sN, 16);
            u64 qR = __shfl_xor_sync(0xffffffffu, tR, 16);
            u64 qZ = __shfl_xor_sync(0xffffffffu, tZ, 16);
            u64 qN = __shfl_xor_sync(0xffffffffu, tN, 16);
            u64 oR = kh ? aRB : aRA;  u64 oZ = kh ? aZB : aZA;  u64 oN = kh ? aNB : aNA;
            u64 pR = kh ? bRB : bRA;  u64 pZ = kh ? bZB : bZA;  u64 pN = kh ? bNB : bNA;
            float2 x1, x2v;
            x1 = unpack2(oR); x2v = unpack2(rR); float ir = x1.x + x1.y + x2v.x + x2v.y + sBi[j];
            x1 = unpack2(oZ); x2v = unpack2(rZ); float iz = x1.x + x1.y + x2v.x + x2v.y + sBi[64 + j];
            x1 = unpack2(oN); x2v = unpack2(rN); float in_ = x1.x + x1.y + x2v.x + x2v.y + sBi[128 + j];
            x1 = unpack2(pR); x2v = unpack2(qR); float hr = x1.x + x1.y + x2v.x + x2v.y + sBh[j];
            x1 = unpack2(pZ); x2v = unpack2(qZ); float hz = x1.x + x1.y + x2v.x + x2v.y + sBh[64 + j];
            x1 = unpack2(pN); x2v = unpack2(qN); float hn = x1.x + x1.y + x2v.x + x2v.y + sBh[128 + j];
            // h[iE][j]: own half or partner's
            float hsend = hOth[j & 31];
            float hrecv = __shfl_xor_sync(0xffffffffu, hsend, 16);
            float hj = ((j >> 5) == kh) ? hOwn[j & 31] : hrecv;
            float r = sigmf(ir + hr);
            float z = sigmf(iz + hz);
            float ng = tanhfast(in_ + r * hn);
            float hf = scaleE * ((1.f - z) * ng + z * hj);
            s_on += hf * sWon[j];
            s_oe += hf * sWoe[j];
            if (j & 1) {
                pairStore.y = hf;
                if (actE) reinterpret_cast<float2*>(out_h + (size_t)iE * NHID)[j >> 1] = pairStore;
            } else {
                pairStore.x = hf;
            }
        }

        // rare general fallback (both dn,de nonzero) — scalar, global weights
        if (actE && oscaleE != 0.f) {
            s_on = 0.f; s_oe = 0.f;
            float ml[64], hl[64];
            const float* mo = optr + (size_t)iE * NHID;
            const float* ho = g_h + (size_t)iE * NHID;
#pragma unroll
            for (int k = 0; k < 64; k++) { ml[k] = mo[k]; hl[k] = ho[k]; }
            for (int j = 0; j < 64; j++) {
                float ir = gBi[j], iz = gBi[64 + j], in_ = gBi[128 + j];
                float hr = gBh[j], hz = gBh[64 + j], hn = gBh[128 + j];
                for (int k = 0; k < 64; k++) {
                    ir += ml[k] * gWi[j * 64 + k];
                    iz += ml[k] * gWi[(64 + j) * 64 + k];
                    in_ += ml[k] * gWi[(128 + j) * 64 + k];
                    hr += hl[k] * gWh[j * 64 + k];
                    hz += hl[k] * gWh[(64 + j) * 64 + k];
                    hn += hl[k] * gWh[(128 + j) * 64 + k];
                }
                float r = sigmf(ir + hr);
                float z = sigmf(iz + hz);
                float ng = tanhfast(in_ + r * hn);
                float hv = (1.f - z) * ng + z * hl[j];
                size_t oi = (size_t)iE * NHID + j;
                float hf = out_h[oi] + oscaleE * hv;
                out_h[oi] = hf;
                s_on += hf * sWon[j];
                s_oe += hf * sWoe[j];
            }
        }

        if (actE) {
            float y = dnE * (s_on + bon) + deE * (s_oe + boe);
            out[iE] = sigmf(y);
            out[(size_t)N + iE] = y;
        }
    }
}

// ---------------- launch ----------------
extern "C" void kernel_launch(void* const* d_in, const int* in_sizes, int n_in,
                              void* d_out, int out_size) {
    const float* x     = (const float*)d_in[0];
    const float* h_in  = (const float*)d_in[1];
    const int*   nr    = (const int*)d_in[2];
    const int*   nc    = (const int*)d_in[3];
    const float* nv    = (const float*)d_in[4];
    const int*   er    = (const int*)d_in[5];
    const int*   ec    = (const int*)d_in[6];
    const float* ev    = (const float*)d_in[7];
    const float* W1    = (const float*)d_in[8];
    const float* b1    = (const float*)d_in[9];
    const float* gamma = (const float*)d_in[10];
    const float* beta  = (const float*)d_in[11];
    const float* W2    = (const float*)d_in[12];
    const float* b2    = (const float*)d_in[13];
    const float* Wi_n  = (const float*)d_in[14];
    const float* bi_n  = (const float*)d_in[15];
    const float* Wh_n  = (const float*)d_in[16];
    const float* bh_n  = (const float*)d_in[17];
    const float* Wi_e  = (const float*)d_in[18];
    const float* bi_e  = (const float*)d_in[19];
    const float* Wh_e  = (const float*)d_in[20];
    const float* bh_e  = (const float*)d_in[21];
    const float* w_on  = (const float*)d_in[22];
    const float* b_on  = (const float*)d_in[23];
    const float* w_oe  = (const float*)d_in[24];
    const float* b_oe  = (const float*)d_in[25];

    int Nx   = in_sizes[0] / NHID;
    int Nold = in_sizes[1] / NHID;
    int N    = Nx + Nold;
    int nnzN = in_sizes[2];
    int nnzE = in_sizes[5];
    float* out = (float*)d_out;

    cudaFuncSetAttribute(k_gru, cudaFuncAttributeMaxDynamicSharedMemorySize,
                         SMG_TOT * sizeof(float));

    k_init<<<1024, 256>>>((const float4*)h_in, Nold * (NHID / 4), N);

    int tot = nnzN + nnzE;
    k_hist<<<(tot + 255) / 256, 256>>>(nr, nc, nv, nnzN, er, ec, ev, nnzE);

    k_lin1<<<(Nx + 255) / 256, 256>>>(x, W1, b1, Nx);
    k_stats<<<256, 256>>>(Nx);
    k_lin2<<<(Nx + 255) / 256, 256>>>(gamma, beta, W2, b2, Nx, Nold);

    int nblk = (N + 4095) / 4096;
    {
        dim3 g1(nblk, 2);
        k_scan1<<<g1, 256>>>(N);
        k_scan2<<<2, 256>>>(nblk);
        dim3 g3(256, 2);
        k_scan3<<<g3, 256>>>(N);
    }

    k_scatter<<<(tot + 255) / 256, 256>>>(nr, nc, nv, nnzN, er, ec, ev, nnzE);

    {
        long long warps = 2LL * N;
        int blocks = (int)((warps * 32 + 255) / 256);
        k_spmm_csr<<<blocks, 256>>>(N);
    }

    k_gru<<<NSM, 256, SMG_TOT * sizeof(float)>>>(
        Wi_n, bi_n, Wh_n, bh_n, Wi_e, bi_e, Wh_e, bh_e,
        w_on, b_on, w_oe, b_oe, N, out);
}

// round 12
// speedup vs baseline: 1.3670x; 1.1522x over previous
#include <cuda_runtime.h>
#include <math.h>

#define NHID 64
#define NMAX 400000
#define NXMAX 100000
#define NNZCAP 2200000
#define BN_EPS 1e-5f
#define NSM 148

typedef unsigned long long u64;
typedef unsigned int u32;

// ---------------- scratch (device globals; no allocations) ----------------
__device__ __align__(256) float  g_dn[NMAX];
__device__ __align__(256) float  g_de[NMAX];
__device__ __align__(256) float  g_h [NMAX * NHID];
__device__ __align__(256) float  g_mn[NMAX * NHID];
__device__ __align__(256) float  g_me[NMAX * NHID];
__device__ __align__(256) float  g_t [NXMAX * NHID];
__device__ double g_sum[NHID];
__device__ double g_sumsq[NHID];
__device__ __align__(256) int   g_cnt_n[NMAX], g_cnt_e[NMAX];
__device__ __align__(256) int   g_cur_n[NMAX], g_cur_e[NMAX];
__device__ __align__(256) int   g_start_n[NMAX], g_start_e[NMAX];
__device__ __align__(256) int2  g_pkn[NNZCAP], g_pke[NNZCAP];
__device__ int g_bsum_n[4096], g_bsum_e[4096], g_boff_n[4096], g_boff_e[4096];

// ---------------- helpers ----------------
__device__ __forceinline__ u64 pack2(float lo, float hi) {
    u64 r; asm("mov.b64 %0, {%1,%2};" : "=l"(r) : "f"(lo), "f"(hi)); return r;
}
__device__ __forceinline__ float2 unpack2(u64 v) {
    float2 r; asm("mov.b64 {%0,%1}, %2;" : "=f"(r.x), "=f"(r.y) : "l"(v)); return r;
}
__device__ __forceinline__ void fma2(u64& acc, u64 a, u64 b) {
    asm("fma.rn.f32x2 %0, %1, %2, %0;" : "+l"(acc) : "l"(a), "l"(b));
}
__device__ __forceinline__ float sigmf(float x) {
    return __fdividef(1.0f, 1.0f + __expf(-x));
}
__device__ __forceinline__ float tanhfast(float x) {
    return 2.0f * sigmf(2.0f * x) - 1.0f;
}
__device__ __forceinline__ u32 tf32r(float x) {
    u32 r; asm("cvt.rna.tf32.f32 %0, %1;" : "=r"(r) : "f"(x)); return r;
}
__device__ __forceinline__ void cvt2(float x, u32& hi, u32& lo) {
    hi = tf32r(x);
    lo = tf32r(x - __uint_as_float(hi));
}
__device__ __forceinline__ void mma_tf32(float* d, const u32* a, u32 b0, u32 b1) {
    asm volatile(
        "mma.sync.aligned.m16n8k8.row.col.f32.tf32.tf32.f32 "
        "{%0,%1,%2,%3},{%4,%5,%6,%7},{%8,%9},{%0,%1,%2,%3};"
        : "+f"(d[0]), "+f"(d[1]), "+f"(d[2]), "+f"(d[3])
        : "r"(a[0]), "r"(a[1]), "r"(a[2]), "r"(a[3]), "r"(b0), "r"(b1));
}

// ---------------- K0: zero scratch + copy h_in (merged) ----------------
__global__ void k_init(const float4* __restrict__ h_src, int n4, int N) {
    int i = blockIdx.x * blockDim.x + threadIdx.x;
    int stride = gridDim.x * blockDim.x;
    float4* dst = reinterpret_cast<float4*>(g_h);
    for (int j = i; j < n4; j += stride) dst[j] = h_src[j];
    for (int j = i; j < N; j += stride) {
        g_dn[j] = 0.f; g_de[j] = 0.f;
        g_cnt_n[j] = 0; g_cnt_e[j] = 0;
        g_cur_n[j] = 0; g_cur_e[j] = 0;
    }
    if (i < NHID) { g_sum[i] = 0.0; g_sumsq[i] = 0.0; }
}

// ---------------- K1: histogram + diagonal extraction ----------------
__global__ void k_hist(const int* __restrict__ nr, const int* __restrict__ nc,
                       const float* __restrict__ nv, int nnzN,
                       const int* __restrict__ er, const int* __restrict__ ec,
                       const float* __restrict__ ev, int nnzE) {
    int j = blockIdx.x * blockDim.x + threadIdx.x;
    int tot = nnzN + nnzE;
    if (j >= tot) return;
    if (j < nnzN) {
        int r = nr[j], c = nc[j];
        if (r == c) atomicAdd(&g_dn[r], nv[j]);
        else atomicAdd(&g_cnt_n[r], 1);
    } else {
        int e = j - nnzN;
        int r = er[e], c = ec[e];
        if (r == c) atomicAdd(&g_de[r], ev[e]);
        else atomicAdd(&g_cnt_e[r], 1);
    }
}

// ---------------- scans (blockIdx.y: 0=node, 1=edge) ----------------
__global__ void k_scan1(int n) {
    int edge = blockIdx.y;
    const int* in = edge ? g_cnt_e : g_cnt_n;
    int* out = edge ? g_start_e : g_start_n;
    int* bsum = edge ? g_bsum_e : g_bsum_n;
    __shared__ int sh[256];
    int tid = threadIdx.x;
    int base = blockIdx.x * 4096 + tid * 16;
    int loc[16]; int s = 0;
#pragma unroll
    for (int k = 0; k < 16; k++) {
        loc[k] = (base + k < n) ? in[base + k] : 0;
        s += loc[k];
    }
    sh[tid] = s; __syncthreads();
    for (int off = 1; off < 256; off <<= 1) {
        int t2 = (tid >= off) ? sh[tid - off] : 0;
        __syncthreads();
        sh[tid] += t2;
        __syncthreads();
    }
    int incl = sh[tid];
    int run = incl - s;
#pragma unroll
    for (int k = 0; k < 16; k++) {
        if (base + k < n) out[base + k] = run;
        run += loc[k];
    }
    if (tid == 255) bsum[blockIdx.x] = incl;
}

__global__ void k_scan2(int nblk) {
    int edge = blockIdx.x;
    const int* bsum = edge ? g_bsum_e : g_bsum_n;
    int* boff = edge ? g_boff_e : g_boff_n;
    __shared__ int sh[256];
    int tid = threadIdx.x;
    int base = tid * 16;
    int loc[16]; int s = 0;
#pragma unroll
    for (int k = 0; k < 16; k++) {
        loc[k] = (base + k < nblk) ? bsum[base + k] : 0;
        s += loc[k];
    }
    sh[tid] = s; __syncthreads();
    for (int off = 1; off < 256; off <<= 1) {
        int t2 = (tid >= off) ? sh[tid - off] : 0;
        __syncthreads();
        sh[tid] += t2;
        __syncthreads();
    }
    int incl = sh[tid];
    int run = incl - s;
#pragma unroll
    for (int k = 0; k < 16; k++) {
        if (base + k < nblk) boff[base + k] = run;
        run += loc[k];
    }
}

__global__ void k_scan3(int n) {
    int edge = blockIdx.y;
    int* out = edge ? g_start_e : g_start_n;
    const int* boff = edge ? g_boff_e : g_boff_n;
    int i = blockIdx.x * blockDim.x + threadIdx.x;
    int stride = gridDim.x * blockDim.x;
    for (int j = i; j < n; j += stride) out[j] += boff[j >> 12];
}

// ---------------- K-scatter: build packed CSR, filtered ----------------
__global__ void k_scatter(const int* __restrict__ nr, const int* __restrict__ nc,
                          const float* __restrict__ nv, int nnzN,
                          const int* __restrict__ er, const int* __restrict__ ec,
                          const float* __restrict__ ev, int nnzE) {
    int j = blockIdx.x * blockDim.x + threadIdx.x;
    int tot = nnzN + nnzE;
    if (j >= tot) return;
    if (j < nnzN) {
        int r = nr[j], c = nc[j];
        if (r != c && g_dn[r] != 0.f) {
            int p = g_start_n[r] + atomicAdd(&g_cur_n[r], 1);
            g_pkn[p] = make_int2(c, __float_as_int(nv[j]));
        }
    } else {
        int e = j - nnzN;
        int r = er[e], c = ec[e];
        if (r != c && g_de[r] != 0.f) {
            int p = g_start_e[r] + atomicAdd(&g_cur_e[r], 1);
            g_pke[p] = make_int2(c, __float_as_int(ev[e]));
        }
    }
}

// ---------------- K-spmm CSR: warp per row, 16-lane float4, 2 entries --
__global__ void k_spmm_csr(int N) {
    int w = (blockIdx.x * blockDim.x + threadIdx.x) >> 5;
    int lane = threadIdx.x & 31;
    if (w >= 2 * N) return;
    bool node = w < N;
    int r = node ? w : w - N;
    float scale = node ? g_dn[r] : g_de[r];
    if (scale == 0.f) return;
    const int2* pk = node ? g_pkn : g_pke;
    int s = node ? g_start_n[r] : g_start_e[r];
    int cnt = node ? g_cur_n[r] : g_cur_e[r];
    int half = lane >> 4, l16 = lane & 15;
    float4 acc = make_float4(0.f, 0.f, 0.f, 0.f);
    int p = s, e = s + cnt;
    for (; p + 4 <= e; p += 4) {
        int2 ea = pk[p + half];
        int2 eb = pk[p + 2 + half];
        float4 ha = reinterpret_cast<const float4*>(g_h + (size_t)ea.x * NHID)[l16];
        float4 hb = reinterpret_cast<const float4*>(g_h + (size_t)eb.x * NHID)[l16];
        float va = __int_as_float(ea.y), vb = __int_as_float(eb.y);
        acc.x += va * ha.x + vb * hb.x;
        acc.y += va * ha.y + vb * hb.y;
        acc.z += va * ha.z + vb * hb.z;
        acc.w += va * ha.w + vb * hb.w;
    }
    if (p + 2 <= e) {
        int2 ea = pk[p + half];
        float4 ha = reinterpret_cast<const float4*>(g_h + (size_t)ea.x * NHID)[l16];
        float va = __int_as_float(ea.y);
        acc.x += va * ha.x; acc.y += va * ha.y;
        acc.z += va * ha.z; acc.w += va * ha.w;
        p += 2;
    }
    if (p < e && half == 0) {
        int2 ea = pk[p];
        float4 ha = reinterpret_cast<const float4*>(g_h + (size_t)ea.x * NHID)[l16];
        float va = __int_as_float(ea.y);
        acc.x += va * ha.x; acc.y += va * ha.y;
        acc.z += va * ha.z; acc.w += va * ha.w;
    }
    acc.x += __shfl_xor_sync(0xffffffffu, acc.x, 16);
    acc.y += __shfl_xor_sync(0xffffffffu, acc.y, 16);
    acc.z += __shfl_xor_sync(0xffffffffu, acc.z, 16);
    acc.w += __shfl_xor_sync(0xffffffffu, acc.w, 16);
    if (half == 0) {
        float* M = node ? g_mn : g_me;
        reinterpret_cast<float4*>(M + (size_t)r * NHID)[l16] = acc;
    }
}

// ---------------- K3: lin1, thread-per-row ----------------
__global__ void __launch_bounds__(256) k_lin1(
    const float* __restrict__ x, const float* __restrict__ W1,
    const float* __restrict__ b1, int Nx) {
    __shared__ float sW[4096];
    __shared__ float sB[64];
    int tid = threadIdx.x;
    for (int t = tid; t < 4096; t += 256) sW[t] = W1[t];
    if (tid < 64) sB[tid] = b1[tid];
    __syncthreads();
    int i = blockIdx.x * 256 + tid;
    if (i >= Nx) return;
    u64 x2[32];
    const ulonglong2* xr = reinterpret_cast<const ulonglong2*>(x + (size_t)i * NHID);
#pragma unroll
    for (int k = 0; k < 16; k++) { ulonglong2 v = xr[k]; x2[2 * k] = v.x; x2[2 * k + 1] = v.y; }
    float4* o = reinterpret_cast<float4*>(g_t + (size_t)i * NHID);
    for (int jg = 0; jg < 16; jg++) {
        float res[4];
#pragma unroll
        for (int jj = 0; jj < 4; jj++) {
            int j = jg * 4 + jj;
            u64 acc = pack2(sB[j], 0.f);
            const ulonglong2* wr = reinterpret_cast<const ulonglong2*>(sW + j * 64);
#pragma unroll
            for (int k = 0; k < 16; k++) {
                ulonglong2 wv = wr[k];
                fma2(acc, x2[2 * k], wv.x);
                fma2(acc, x2[2 * k + 1], wv.y);
            }
            float2 p = unpack2(acc);
            res[jj] = p.x + p.y;
        }
        o[jg] = make_float4(res[0], res[1], res[2], res[3]);
    }
}

// ---------------- K-stats ----------------
__global__ void k_stats(int Nx) {
    __shared__ float sS[64], sQ[64];
    int tid = threadIdx.x;
    if (tid < 64) { sS[tid] = 0.f; sQ[tid] = 0.f; }
    __syncthreads();
    int cc = tid & 15;
    float4 s = make_float4(0.f, 0.f, 0.f, 0.f);
    float4 q = make_float4(0.f, 0.f, 0.f, 0.f);
    for (int r = blockIdx.x * 16 + (tid >> 4); r < Nx; r += gridDim.x * 16) {
        float4 v = reinterpret_cast<const float4*>(g_t)[(size_t)r * 16 + cc];
        s.x += v.x; s.y += v.y; s.z += v.z; s.w += v.w;
        q.x += v.x * v.x; q.y += v.y * v.y; q.z += v.z * v.z; q.w += v.w * v.w;
    }
    int c0 = cc * 4;
    atomicAdd(&sS[c0], s.x); atomicAdd(&sS[c0 + 1], s.y);
    atomicAdd(&sS[c0 + 2], s.z); atomicAdd(&sS[c0 + 3], s.w);
    atomicAdd(&sQ[c0], q.x); atomicAdd(&sQ[c0 + 1], q.y);
    atomicAdd(&sQ[c0 + 2], q.z); atomicAdd(&sQ[c0 + 3], q.w);
    __syncthreads();
    if (tid < 64) {
        atomicAdd(&g_sum[tid], (double)sS[tid]);
        atomicAdd(&g_sumsq[tid], (double)sQ[tid]);
    }
}

// ---------------- K4: BN + ReLU + lin2 + h_update ----------------
__global__ void __launch_bounds__(256) k_lin2(
    const float* __restrict__ gamma, const float* __restrict__ beta,
    const float* __restrict__ W2, const float* __restrict__ b2,
    int Nx, int Nold) {
    __shared__ float sW[4096];
    __shared__ float sB[64];
    __shared__ float sScale[64], sShift[64];
    int tid = threadIdx.x;
    for (int t = tid; t < 4096; t += 256) sW[t] = W2[t];
    if (tid < 64) {
        sB[tid] = b2[tid];
        double mu = g_sum[tid] / (double)Nx;
        double var = g_sumsq[tid] / (double)Nx - mu * mu;
        float inv = rsqrtf((float)var + BN_EPS);
        float sc = gamma[tid] * inv;
        sScale[tid] = sc;
        sShift[tid] = beta[tid] - (float)mu * sc;
    }
    __syncthreads();
    int i = blockIdx.x * 256 + tid;
    if (i >= Nx) return;
    u64 x2[32];
    const float4* tr = reinterpret_cast<const float4*>(g_t + (size_t)i * NHID);
#pragma unroll
    for (int k = 0; k < 16; k++) {
        float4 v = tr[k];
        int k0 = k * 4;
        v.x = fmaxf(v.x * sScale[k0] + sShift[k0], 0.f);
        v.y = fmaxf(v.y * sScale[k0 + 1] + sShift[k0 + 1], 0.f);
        v.z = fmaxf(v.z * sScale[k0 + 2] + sShift[k0 + 2], 0.f);
        v.w = fmaxf(v.w * sScale[k0 + 3] + sShift[k0 + 3], 0.f);
        x2[2 * k] = pack2(v.x, v.y);
        x2[2 * k + 1] = pack2(v.z, v.w);
    }
    float dn = g_dn[Nold + i];
    float4* o = reinterpret_cast<float4*>(g_h + (size_t)(Nold + i) * NHID);
    for (int jg = 0; jg < 16; jg++) {
        float res[4];
#pragma unroll
        for (int jj = 0; jj < 4; jj++) {
            int j = jg * 4 + jj;
            u64 acc = pack2(sB[j], 0.f);
            const ulonglong2* wr = reinterpret_cast<const ulonglong2*>(sW + j * 64);
#pragma unroll
            for (int k = 0; k < 16; k++) {
                ulonglong2 wv = wr[k];
                fma2(acc, x2[2 * k], wv.x);
                fma2(acc, x2[2 * k + 1], wv.y);
            }
            float2 p = unpack2(acc);
            res[jj] = (p.x + p.y) * dn;
        }
        o[jg] = make_float4(res[0], res[1], res[2], res[3]);
    }
}

// ---------------- K6: persistent GRU via tf32 tensor cores (3xTF32) ----
// smem: 4 weight matrices [192][68] floats (stride-68 pad, conflict-free
// B-fragment loads), then biases (768), then head weights (128).
#define SW_STRIDE 68
#define SW_MAT    (192 * SW_STRIDE)      // 13056 floats
#define SMW_TOT   (4 * SW_MAT)           // 52224 floats
#define SMB_OFF   SMW_TOT
#define SMH_OFF   (SMW_TOT + 768)
#define SMG_TOTF  (SMW_TOT + 768 + 128)  // 53120 floats = 212480 B

__global__ void __launch_bounds__(256) k_gru(
    const float* __restrict__ Wi_n, const float* __restrict__ bi_n,
    const float* __restrict__ Wh_n, const float* __restrict__ bh_n,
    const float* __restrict__ Wi_e, const float* __restrict__ bi_e,
    const float* __restrict__ Wh_e, const float* __restrict__ bh_e,
    const float* __restrict__ w_on, const float* __restrict__ b_on,
    const float* __restrict__ w_oe, const float* __restrict__ b_oe,
    int N, float* __restrict__ out) {
    extern __shared__ float sm[];
    int tid = threadIdx.x;
    // stage weights: sm[mat*SW_MAT + j*68 + k] = W[mat][j*64+k]
    for (int s = tid; s < 4 * 192 * 64; s += 256) {
        int mat = s / 12288, rem = s % 12288;
        int j = rem >> 6, k = rem & 63;
        const float* src = (mat == 0) ? Wi_n : (mat == 1) ? Wh_n
                          : (mat == 2) ? Wi_e : Wh_e;
        sm[mat * SW_MAT + j * SW_STRIDE + k] = src[rem];
    }
    if (tid < 192) {
        sm[SMB_OFF + tid] = bi_n[tid];
        sm[SMB_OFF + 192 + tid] = bh_n[tid];
        sm[SMB_OFF + 384 + tid] = bi_e[tid];
        sm[SMB_OFF + 576 + tid] = bh_e[tid];
    }
    if (tid < 64) {
        sm[SMH_OFF + tid] = w_on[tid];
        sm[SMH_OFF + 64 + tid] = w_oe[tid];
    }
    __syncthreads();

    int wid = tid >> 5, lane = tid & 31;
    int g = lane >> 2, t = lane & 3;
    bool isNode = wid < 4;
    int wl = isNode ? wid : wid - 4;
    int par = isNode ? 0 : 1;
    const float* mptr = isNode ? g_mn : g_me;
    const float* optr = isNode ? g_me : g_mn;
    const float* smWi = sm + (isNode ? 0 : 2) * SW_MAT;
    const float* smWh = sm + (isNode ? 1 : 3) * SW_MAT;
    const float* sBi = sm + SMB_OFF + (isNode ? 0 : 384);
    const float* sBh = sm + SMB_OFF + (isNode ? 192 : 576);
    const float* gWi = isNode ? Wi_e : Wi_n;
    const float* gWh = isNode ? Wh_e : Wh_n;
    const float* gBi = isNode ? bi_e : bi_n;
    const float* gBh = isNode ? bh_e : bh_n;
    const float* sWon = sm + SMH_OFF;
    const float* sWoe = sm + SMH_OFF + 64;
    float* out_h = out + 2 * (size_t)N;
    float bon = b_on[0], boe = b_oe[0];

    u32 Amh[32], Aml[32], Ahh[32], Ahl[32];

    for (int base = blockIdx.x * 128; base < N; base += gridDim.x * 128) {
        int r0 = base + 2 * (wl * 16 + g) + par;
        int r1 = r0 + 16;
        bool act0 = r0 < N, act1 = r1 < N;
        float dn0 = act0 ? g_dn[r0] : 0.f, de0 = act0 ? g_de[r0] : 0.f;
        float dn1 = act1 ? g_dn[r1] : 0.f, de1 = act1 ? g_de[r1] : 0.f;
        float scale0 = isNode ? dn0 : de0;
        float scale1 = isNode ? dn1 : de1;
        float oscale0 = isNode ? de0 : dn0;
        float oscale1 = isNode ? de1 : dn1;

        // load + convert A fragments (m and h) for all 8 k-tiles
#pragma unroll
        for (int kt = 0; kt < 8; kt++) {
            int c = kt * 8 + t;
            float v0 = act0 ? mptr[(size_t)r0 * 64 + c] : 0.f;
            float v1 = act1 ? mptr[(size_t)r1 * 64 + c] : 0.f;
            float v2 = act0 ? mptr[(size_t)r0 * 64 + c + 4] : 0.f;
            float v3 = act1 ? mptr[(size_t)r1 * 64 + c + 4] : 0.f;
            cvt2(v0, Amh[kt * 4 + 0], Aml[kt * 4 + 0]);
            cvt2(v1, Amh[kt * 4 + 1], Aml[kt * 4 + 1]);
            cvt2(v2, Amh[kt * 4 + 2], Aml[kt * 4 + 2]);
            cvt2(v3, Amh[kt * 4 + 3], Aml[kt * 4 + 3]);
            float w0 = act0 ? g_h[(size_t)r0 * 64 + c] : 0.f;
            float w1 = act1 ? g_h[(size_t)r1 * 64 + c] : 0.f;
            float w2 = act0 ? g_h[(size_t)r0 * 64 + c + 4] : 0.f;
            float w3 = act1 ? g_h[(size_t)r1 * 64 + c + 4] : 0.f;
            cvt2(w0, Ahh[kt * 4 + 0], Ahl[kt * 4 + 0]);
            cvt2(w1, Ahh[kt * 4 + 1], Ahl[kt * 4 + 1]);
            cvt2(w2, Ahh[kt * 4 + 2], Ahl[kt * 4 + 2]);
            cvt2(w3, Ahh[kt * 4 + 3], Ahl[kt * 4 + 3]);
        }

        float s_on0 = 0.f, s_oe0 = 0.f, s_on1 = 0.f, s_oe1 = 0.f;

        for (int q = 0; q < 8; q++) {
            float Dir[4] = {0,0,0,0}, Diz[4] = {0,0,0,0}, Din[4] = {0,0,0,0};
            float Dhr[4] = {0,0,0,0}, Dhz[4] = {0,0,0,0}, Dhn[4] = {0,0,0,0};
            int nr_ = (q * 8 + g) * SW_STRIDE;
            int nz_ = ((64 + q * 8) + g) * SW_STRIDE;
            int nn_ = ((128 + q * 8) + g) * SW_STRIDE;
#pragma unroll
            for (int kt = 0; kt < 8; kt++) {
                int kc = kt * 8 + t;
                u32 bh0, bl0, bh1, bl1;
                // Wi: r gate
                cvt2(smWi[nr_ + kc], bh0, bl0);
                cvt2(smWi[nr_ + kc + 4], bh1, bl1);
                mma_tf32(Dir, &Amh[kt * 4], bh0, bh1);
                mma_tf32(Dir, &Amh[kt * 4], bl0, bl1);
                mma_tf32(Dir, &Aml[kt * 4], bh0, bh1);
                // Wi: z gate
                cvt2(smWi[nz_ + kc], bh0, bl0);
                cvt2(smWi[nz_ + kc + 4], bh1, bl1);
                mma_tf32(Diz, &Amh[kt * 4], bh0, bh1);
                mma_tf32(Diz, &Amh[kt * 4], bl0, bl1);
                mma_tf32(Diz, &Aml[kt * 4], bh0, bh1);
                // Wi: n gate
                cvt2(smWi[nn_ + kc], bh0, bl0);
                cvt2(smWi[nn_ + kc + 4], bh1, bl1);
                mma_tf32(Din, &Amh[kt * 4], bh0, bh1);
                mma_tf32(Din, &Amh[kt * 4], bl0, bl1);
                mma_tf32(Din, &Aml[kt * 4], bh0, bh1);
                // Wh: r gate
                cvt2(smWh[nr_ + kc], bh0, bl0);
                cvt2(smWh[nr_ + kc + 4], bh1, bl1);
                mma_tf32(Dhr, &Ahh[kt * 4], bh0, bh1);
                mma_tf32(Dhr, &Ahh[kt * 4], bl0, bl1);
                mma_tf32(Dhr, &Ahl[kt * 4], bh0, bh1);
                // Wh: z gate
                cvt2(smWh[nz_ + kc], bh0, bl0);
                cvt2(smWh[nz_ + kc + 4], bh1, bl1);
                mma_tf32(Dhz, &Ahh[kt * 4], bh0, bh1);
                mma_tf32(Dhz, &Ahh[kt * 4], bl0, bl1);
                mma_tf32(Dhz, &Ahl[kt * 4], bh0, bh1);
                // Wh: n gate
                cvt2(smWh[nn_ + kc], bh0, bl0);
                cvt2(smWh[nn_ + kc + 4], bh1, bl1);
                mma_tf32(Dhn, &Ahh[kt * 4], bh0, bh1);
                mma_tf32(Dhn, &Ahh[kt * 4], bl0, bl1);
                mma_tf32(Dhn, &Ahl[kt * 4], bh0, bh1);
            }
            // epilogue: rows (g -> r0: c0,c1), (g+8 -> r1: c2,c3); cols j0, j0+1
            int j0 = q * 8 + 2 * t;
            float2 hp0 = act0 ? *reinterpret_cast<const float2*>(g_h + (size_t)r0 * 64 + j0)
                              : make_float2(0.f, 0.f);
            float2 hp1 = act1 ? *reinterpret_cast<const float2*>(g_h + (size_t)r1 * 64 + j0)
                              : make_float2(0.f, 0.f);
            float hf[4];
#pragma unroll
            for (int e = 0; e < 4; e++) {
                int rowSel = e >> 1;
                int j = j0 + (e & 1);
                int ci = rowSel * 2 + (e & 1);
                float ir = Dir[ci] + sBi[j];
                float iz = Diz[ci] + sBi[64 + j];
                float in_ = Din[ci] + sBi[128 + j];
                float hr = Dhr[ci] + sBh[j];
                float hz = Dhz[ci] + sBh[64 + j];
                float hn = Dhn[ci] + sBh[128 + j];
                float hj = rowSel ? ((e & 1) ? hp1.y : hp1.x)
                                  : ((e & 1) ? hp0.y : hp0.x);
                float sc = rowSel ? scale1 : scale0;
                float r = sigmf(ir + hr);
                float z = sigmf(iz + hz);
                float ng = tanhfast(in_ + r * hn);
                hf[e] = sc * ((1.f - z) * ng + z * hj);
                float won = sWon[j], woe = sWoe[j];
                if (rowSel) { s_on1 += hf[e] * won; s_oe1 += hf[e] * woe; }
                else        { s_on0 += hf[e] * won; s_oe0 += hf[e] * woe; }
            }
            if (act0) *reinterpret_cast<float2*>(out_h + (size_t)r0 * 64 + j0) = make_float2(hf[0], hf[1]);
            if (act1) *reinterpret_cast<float2*>(out_h + (size_t)r1 * 64 + j0) = make_float2(hf[2], hf[3]);
        }

        // reduce head sums across the 4 lanes of each row group
        s_on0 += __shfl_xor_sync(0xffffffffu, s_on0, 1);
        s_on0 += __shfl_xor_sync(0xffffffffu, s_on0, 2);
        s_oe0 += __shfl_xor_sync(0xffffffffu, s_oe0, 1);
        s_oe0 += __shfl_xor_sync(0xffffffffu, s_oe0, 2);
        s_on1 += __shfl_xor_sync(0xffffffffu, s_on1, 1);
        s_on1 += __shfl_xor_sync(0xffffffffu, s_on1, 2);
        s_oe1 += __shfl_xor_sync(0xffffffffu, s_oe1, 1);
        s_oe1 += __shfl_xor_sync(0xffffffffu, s_oe1, 2);
        __syncwarp();

        if (t == 0) {
#pragma unroll
            for (int rowSel = 0; rowSel < 2; rowSel++) {
                int rr = rowSel ? r1 : r0;
                bool act = rowSel ? act1 : act0;
                if (!act) continue;
                float dnr = rowSel ? dn1 : dn0;
                float der = rowSel ? de1 : de0;
                float osc = rowSel ? oscale1 : oscale0;
                float son = rowSel ? s_on1 : s_on0;
                float soe = rowSel ? s_oe1 : s_oe0;
                if (osc != 0.f) {
                    // rare general fallback: add other-GRU contribution (scalar)
                    son = 0.f; soe = 0.f;
                    float ml[64], hl[64];
                    const float* mo = optr + (size_t)rr * 64;
                    const float* ho = g_h + (size_t)rr * 64;
                    for (int k = 0; k < 64; k++) { ml[k] = mo[k]; hl[k] = ho[k]; }
                    for (int j = 0; j < 64; j++) {
                        float ir = gBi[j], iz = gBi[64 + j], in_ = gBi[128 + j];
                        float hr = gBh[j], hz = gBh[64 + j], hn = gBh[128 + j];
                        for (int k = 0; k < 64; k++) {
                            ir += ml[k] * gWi[j * 64 + k];
                            iz += ml[k] * gWi[(64 + j) * 64 + k];
                            in_ += ml[k] * gWi[(128 + j) * 64 + k];
                            hr += hl[k] * gWh[j * 64 + k];
                            hz += hl[k] * gWh[(64 + j) * 64 + k];
                            hn += hl[k] * gWh[(128 + j) * 64 + k];
                        }
                        float r = sigmf(ir + hr);
                        float z = sigmf(iz + hz);
                        float ng = tanhfast(in_ + r * hn);
                        float hv = (1.f - z) * ng + z * hl[j];
                        size_t oi = (size_t)rr * 64 + j;
                        float hfv = out_h[oi] + osc * hv;
                        out_h[oi] = hfv;
                        son += hfv * sWon[j];
                        soe += hfv * sWoe[j];
                    }
                }
                float y = dnr * (son + bon) + der * (soe + boe);
                out[rr] = sigmf(y);
                out[(size_t)N + rr] = y;
            }
        }
    }
}

// ---------------- launch ----------------
extern "C" void kernel_launch(void* const* d_in, const int* in_sizes, int n_in,
                              void* d_out, int out_size) {
    const float* x     = (const float*)d_in[0];
    const float* h_in  = (const float*)d_in[1];
    const int*   nr    = (const int*)d_in[2];
    const int*   nc    = (const int*)d_in[3];
    const float* nv    = (const float*)d_in[4];
    const int*   er    = (const int*)d_in[5];
    const int*   ec    = (const int*)d_in[6];
    const float* ev    = (const float*)d_in[7];
    const float* W1    = (const float*)d_in[8];
    const float* b1    = (const float*)d_in[9];
    const float* gamma = (const float*)d_in[10];
    const float* beta  = (const float*)d_in[11];
    const float* W2    = (const float*)d_in[12];
    const float* b2    = (const float*)d_in[13];
    const float* Wi_n  = (const float*)d_in[14];
    const float* bi_n  = (const float*)d_in[15];
    const float* Wh_n  = (const float*)d_in[16];
    const float* bh_n  = (const float*)d_in[17];
    const float* Wi_e  = (const float*)d_in[18];
    const float* bi_e  = (const float*)d_in[19];
    const float* Wh_e  = (const float*)d_in[20];
    const float* bh_e  = (const float*)d_in[21];
    const float* w_on  = (const float*)d_in[22];
    const float* b_on  = (const float*)d_in[23];
    const float* w_oe  = (const float*)d_in[24];
    const float* b_oe  = (const float*)d_in[25];

    int Nx   = in_sizes[0] / NHID;
    int Nold = in_sizes[1] / NHID;
    int N    = Nx + Nold;
    int nnzN = in_sizes[2];
    int nnzE = in_sizes[5];
    float* out = (float*)d_out;

    cudaFuncSetAttribute(k_gru, cudaFuncAttributeMaxDynamicSharedMemorySize,
                         SMG_TOTF * sizeof(float));

    k_init<<<1024, 256>>>((const float4*)h_in, Nold * (NHID / 4), N);

    int tot = nnzN + nnzE;
    k_hist<<<(tot + 255) / 256, 256>>>(nr, nc, nv, nnzN, er, ec, ev, nnzE);

    k_lin1<<<(Nx + 255) / 256, 256>>>(x, W1, b1, Nx);
    k_stats<<<256, 256>>>(Nx);
    k_lin2<<<(Nx + 255) / 256, 256>>>(gamma, beta, W2, b2, Nx, Nold);

    int nblk = (N + 4095) / 4096;
    {
        dim3 g1(nblk, 2);
        k_scan1<<<g1, 256>>>(N);
        k_scan2<<<2, 256>>>(nblk);
        dim3 g3(256, 2);
        k_scan3<<<g3, 256>>>(N);
    }

    k_scatter<<<(tot + 255) / 256, 256>>>(nr, nc, nv, nnzN, er, ec, ev, nnzE);

    {
        long long warps = 2LL * N;
        int blocks = (int)((warps * 32 + 255) / 256);
        k_spmm_csr<<<blocks, 256>>>(N);
    }

    k_gru<<<NSM, 256, SMG_TOTF * sizeof(float)>>>(
        Wi_n, bi_n, Wh_n, bh_n, Wi_e, bi_e, Wh_e, bh_e,
        w_on, b_on, w_oe, b_oe, N, out);
}

// round 13
// speedup vs baseline: 1.5079x; 1.1031x over previous
#include <cuda_runtime.h>
#include <math.h>

#define NHID 64
#define NMAX 400000
#define NXMAX 100000
#define NNZCAP 2200000
#define BN_EPS 1e-5f
#define NSM 148

typedef unsigned long long u64;
typedef unsigned int u32;

// ---------------- scratch (device globals; no allocations) ----------------
__device__ __align__(256) float  g_dn[NMAX];
__device__ __align__(256) float  g_de[NMAX];
__device__ __align__(256) float  g_h [NMAX * NHID];
__device__ __align__(256) float  g_mn[NMAX * NHID];
__device__ __align__(256) float  g_me[NMAX * NHID];
__device__ __align__(256) float  g_t [NXMAX * NHID];
__device__ double g_sum[NHID];
__device__ double g_sumsq[NHID];
__device__ __align__(256) int   g_cnt_n[NMAX], g_cnt_e[NMAX];
__device__ __align__(256) int   g_cur_n[NMAX], g_cur_e[NMAX];
__device__ __align__(256) int   g_start_n[NMAX], g_start_e[NMAX];
__device__ __align__(256) int2  g_pkn[NNZCAP], g_pke[NNZCAP];
__device__ int g_bsum_n[4096], g_bsum_e[4096], g_boff_n[4096], g_boff_e[4096];

// ---------------- helpers ----------------
__device__ __forceinline__ u64 pack2(float lo, float hi) {
    u64 r; asm("mov.b64 %0, {%1,%2};" : "=l"(r) : "f"(lo), "f"(hi)); return r;
}
__device__ __forceinline__ float2 unpack2(u64 v) {
    float2 r; asm("mov.b64 {%0,%1}, %2;" : "=f"(r.x), "=f"(r.y) : "l"(v)); return r;
}
__device__ __forceinline__ void fma2(u64& acc, u64 a, u64 b) {
    asm("fma.rn.f32x2 %0, %1, %2, %0;" : "+l"(acc) : "l"(a), "l"(b));
}
__device__ __forceinline__ float sigmf(float x) {
    return __fdividef(1.0f, 1.0f + __expf(-x));
}
__device__ __forceinline__ float tanhfast(float x) {
    return 2.0f * sigmf(2.0f * x) - 1.0f;
}
__device__ __forceinline__ u32 tf32r(float x) {
    u32 r; asm("cvt.rna.tf32.f32 %0, %1;" : "=r"(r) : "f"(x)); return r;
}
__device__ __forceinline__ void cvt2(float x, u32& hi, u32& lo) {
    hi = tf32r(x);
    lo = tf32r(x - __uint_as_float(hi));
}
__device__ __forceinline__ void mma_tf32(float* d, const u32* a, u32 b0, u32 b1) {
    asm volatile(
        "mma.sync.aligned.m16n8k8.row.col.f32.tf32.tf32.f32 "
        "{%0,%1,%2,%3},{%4,%5,%6,%7},{%8,%9},{%0,%1,%2,%3};"
        : "+f"(d[0]), "+f"(d[1]), "+f"(d[2]), "+f"(d[3])
        : "r"(a[0]), "r"(a[1]), "r"(a[2]), "r"(a[3]), "r"(b0), "r"(b1));
}

// ---------------- K0: zero scratch + copy h_in (merged) ----------------
__global__ void k_init(const float4* __restrict__ h_src, int n4, int N) {
    int i = blockIdx.x * blockDim.x + threadIdx.x;
    int stride = gridDim.x * blockDim.x;
    float4* dst = reinterpret_cast<float4*>(g_h);
    for (int j = i; j < n4; j += stride) dst[j] = h_src[j];
    for (int j = i; j < N; j += stride) {
        g_dn[j] = 0.f; g_de[j] = 0.f;
        g_cnt_n[j] = 0; g_cnt_e[j] = 0;
        g_cur_n[j] = 0; g_cur_e[j] = 0;
    }
    if (i < NHID) { g_sum[i] = 0.0; g_sumsq[i] = 0.0; }
}

// ---------------- K1: histogram + diagonal extraction ----------------
__global__ void k_hist(const int* __restrict__ nr, const int* __restrict__ nc,
                       const float* __restrict__ nv, int nnzN,
                       const int* __restrict__ er, const int* __restrict__ ec,
                       const float* __restrict__ ev, int nnzE) {
    int j = blockIdx.x * blockDim.x + threadIdx.x;
    int tot = nnzN + nnzE;
    if (j >= tot) return;
    if (j < nnzN) {
        int r = nr[j], c = nc[j];
        if (r == c) atomicAdd(&g_dn[r], nv[j]);
        else atomicAdd(&g_cnt_n[r], 1);
    } else {
        int e = j - nnzN;
        int r = er[e], c = ec[e];
        if (r == c) atomicAdd(&g_de[r], ev[e]);
        else atomicAdd(&g_cnt_e[r], 1);
    }
}

// ---------------- scans (blockIdx.y: 0=node, 1=edge) ----------------
__global__ void k_scan1(int n) {
    int edge = blockIdx.y;
    const int* in = edge ? g_cnt_e : g_cnt_n;
    int* out = edge ? g_start_e : g_start_n;
    int* bsum = edge ? g_bsum_e : g_bsum_n;
    __shared__ int sh[256];
    int tid = threadIdx.x;
    int base = blockIdx.x * 4096 + tid * 16;
    int loc[16]; int s = 0;
#pragma unroll
    for (int k = 0; k < 16; k++) {
        loc[k] = (base + k < n) ? in[base + k] : 0;
        s += loc[k];
    }
    sh[tid] = s; __syncthreads();
    for (int off = 1; off < 256; off <<= 1) {
        int t2 = (tid >= off) ? sh[tid - off] : 0;
        __syncthreads();
        sh[tid] += t2;
        __syncthreads();
    }
    int incl = sh[tid];
    int run = incl - s;
#pragma unroll
    for (int k = 0; k < 16; k++) {
        if (base + k < n) out[base + k] = run;
        run += loc[k];
    }
    if (tid == 255) bsum[blockIdx.x] = incl;
}

__global__ void k_scan2(int nblk) {
    int edge = blockIdx.x;
    const int* bsum = edge ? g_bsum_e : g_bsum_n;
    int* boff = edge ? g_boff_e : g_boff_n;
    __shared__ int sh[256];
    int tid = threadIdx.x;
    int base = tid * 16;
    int loc[16]; int s = 0;
#pragma unroll
    for (int k = 0; k < 16; k++) {
        loc[k] = (base + k < nblk) ? bsum[base + k] : 0;
        s += loc[k];
    }
    sh[tid] = s; __syncthreads();
    for (int off = 1; off < 256; off <<= 1) {
        int t2 = (tid >= off) ? sh[tid - off] : 0;
        __syncthreads();
        sh[tid] += t2;
        __syncthreads();
    }
    int incl = sh[tid];
    int run = incl - s;
#pragma unroll
    for (int k = 0; k < 16; k++) {
        if (base + k < nblk) boff[base + k] = run;
        run += loc[k];
    }
}

__global__ void k_scan3(int n) {
    int edge = blockIdx.y;
    int* out = edge ? g_start_e : g_start_n;
    const int* boff = edge ? g_boff_e : g_boff_n;
    int i = blockIdx.x * blockDim.x + threadIdx.x;
    int stride = gridDim.x * blockDim.x;
    for (int j = i; j < n; j += stride) out[j] += boff[j >> 12];
}

// ---------------- K-scatter: build packed CSR, filtered ----------------
__global__ void k_scatter(const int* __restrict__ nr, const int* __restrict__ nc,
                          const float* __restrict__ nv, int nnzN,
                          const int* __restrict__ er, const int* __restrict__ ec,
                          const float* __restrict__ ev, int nnzE) {
    int j = blockIdx.x * blockDim.x + threadIdx.x;
    int tot = nnzN + nnzE;
    if (j >= tot) return;
    if (j < nnzN) {
        int r = nr[j], c = nc[j];
        if (r != c && g_dn[r] != 0.f) {
            int p = g_start_n[r] + atomicAdd(&g_cur_n[r], 1);
            g_pkn[p] = make_int2(c, __float_as_int(nv[j]));
        }
    } else {
        int e = j - nnzN;
        int r = er[e], c = ec[e];
        if (r != c && g_de[r] != 0.f) {
            int p = g_start_e[r] + atomicAdd(&g_cur_e[r], 1);
            g_pke[p] = make_int2(c, __float_as_int(ev[e]));
        }
    }
}

// ---------------- K-spmm CSR: warp per row, 16-lane float4, 2 entries --
__global__ void k_spmm_csr(int N) {
    int w = (blockIdx.x * blockDim.x + threadIdx.x) >> 5;
    int lane = threadIdx.x & 31;
    if (w >= 2 * N) return;
    bool node = w < N;
    int r = node ? w : w - N;
    float scale = node ? g_dn[r] : g_de[r];
    if (scale == 0.f) return;
    const int2* pk = node ? g_pkn : g_pke;
    int s = node ? g_start_n[r] : g_start_e[r];
    int cnt = node ? g_cur_n[r] : g_cur_e[r];
    int half = lane >> 4, l16 = lane & 15;
    float4 acc = make_float4(0.f, 0.f, 0.f, 0.f);
    int p = s, e = s + cnt;
    for (; p + 4 <= e; p += 4) {
        int2 ea = pk[p + half];
        int2 eb = pk[p + 2 + half];
        float4 ha = reinterpret_cast<const float4*>(g_h + (size_t)ea.x * NHID)[l16];
        float4 hb = reinterpret_cast<const float4*>(g_h + (size_t)eb.x * NHID)[l16];
        float va = __int_as_float(ea.y), vb = __int_as_float(eb.y);
        acc.x += va * ha.x + vb * hb.x;
        acc.y += va * ha.y + vb * hb.y;
        acc.z += va * ha.z + vb * hb.z;
        acc.w += va * ha.w + vb * hb.w;
    }
    if (p + 2 <= e) {
        int2 ea = pk[p + half];
        float4 ha = reinterpret_cast<const float4*>(g_h + (size_t)ea.x * NHID)[l16];
        float va = __int_as_float(ea.y);
        acc.x += va * ha.x; acc.y += va * ha.y;
        acc.z += va * ha.z; acc.w += va * ha.w;
        p += 2;
    }
    if (p < e && half == 0) {
        int2 ea = pk[p];
        float4 ha = reinterpret_cast<const float4*>(g_h + (size_t)ea.x * NHID)[l16];
        float va = __int_as_float(ea.y);
        acc.x += va * ha.x; acc.y += va * ha.y;
        acc.z += va * ha.z; acc.w += va * ha.w;
    }
    acc.x += __shfl_xor_sync(0xffffffffu, acc.x, 16);
    acc.y += __shfl_xor_sync(0xffffffffu, acc.y, 16);
    acc.z += __shfl_xor_sync(0xffffffffu, acc.z, 16);
    acc.w += __shfl_xor_sync(0xffffffffu, acc.w, 16);
    if (half == 0) {
        float* M = node ? g_mn : g_me;
        reinterpret_cast<float4*>(M + (size_t)r * NHID)[l16] = acc;
    }
}

// ---------------- K3: lin1, thread-per-row ----------------
__global__ void __launch_bounds__(256) k_lin1(
    const float* __restrict__ x, const float* __restrict__ W1,
    const float* __restrict__ b1, int Nx) {
    __shared__ float sW[4096];
    __shared__ float sB[64];
    int tid = threadIdx.x;
    for (int t = tid; t < 4096; t += 256) sW[t] = W1[t];
    if (tid < 64) sB[tid] = b1[tid];
    __syncthreads();
    int i = blockIdx.x * 256 + tid;
    if (i >= Nx) return;
    u64 x2[32];
    const ulonglong2* xr = reinterpret_cast<const ulonglong2*>(x + (size_t)i * NHID);
#pragma unroll
    for (int k = 0; k < 16; k++) { ulonglong2 v = xr[k]; x2[2 * k] = v.x; x2[2 * k + 1] = v.y; }
    float4* o = reinterpret_cast<float4*>(g_t + (size_t)i * NHID);
    for (int jg = 0; jg < 16; jg++) {
        float res[4];
#pragma unroll
        for (int jj = 0; jj < 4; jj++) {
            int j = jg * 4 + jj;
            u64 acc = pack2(sB[j], 0.f);
            const ulonglong2* wr = reinterpret_cast<const ulonglong2*>(sW + j * 64);
#pragma unroll
            for (int k = 0; k < 16; k++) {
                ulonglong2 wv = wr[k];
                fma2(acc, x2[2 * k], wv.x);
                fma2(acc, x2[2 * k + 1], wv.y);
            }
            float2 p = unpack2(acc);
            res[jj] = p.x + p.y;
        }
        o[jg] = make_float4(res[0], res[1], res[2], res[3]);
    }
}

// ---------------- K-stats ----------------
__global__ void k_stats(int Nx) {
    __shared__ float sS[64], sQ[64];
    int tid = threadIdx.x;
    if (tid < 64) { sS[tid] = 0.f; sQ[tid] = 0.f; }
    __syncthreads();
    int cc = tid & 15;
    float4 s = make_float4(0.f, 0.f, 0.f, 0.f);
    float4 q = make_float4(0.f, 0.f, 0.f, 0.f);
    for (int r = blockIdx.x * 16 + (tid >> 4); r < Nx; r += gridDim.x * 16) {
        float4 v = reinterpret_cast<const float4*>(g_t)[(size_t)r * 16 + cc];
        s.x += v.x; s.y += v.y; s.z += v.z; s.w += v.w;
        q.x += v.x * v.x; q.y += v.y * v.y; q.z += v.z * v.z; q.w += v.w * v.w;
    }
    int c0 = cc * 4;
    atomicAdd(&sS[c0], s.x); atomicAdd(&sS[c0 + 1], s.y);
    atomicAdd(&sS[c0 + 2], s.z); atomicAdd(&sS[c0 + 3], s.w);
    atomicAdd(&sQ[c0], q.x); atomicAdd(&sQ[c0 + 1], q.y);
    atomicAdd(&sQ[c0 + 2], q.z); atomicAdd(&sQ[c0 + 3], q.w);
    __syncthreads();
    if (tid < 64) {
        atomicAdd(&g_sum[tid], (double)sS[tid]);
        atomicAdd(&g_sumsq[tid], (double)sQ[tid]);
    }
}

// ---------------- K4: BN + ReLU + lin2 + h_update ----------------
__global__ void __launch_bounds__(256) k_lin2(
    const float* __restrict__ gamma, const float* __restrict__ beta,
    const float* __restrict__ W2, const float* __restrict__ b2,
    int Nx, int Nold) {
    __shared__ float sW[4096];
    __shared__ float sB[64];
    __shared__ float sScale[64], sShift[64];
    int tid = threadIdx.x;
    for (int t = tid; t < 4096; t += 256) sW[t] = W2[t];
    if (tid < 64) {
        sB[tid] = b2[tid];
        double mu = g_sum[tid] / (double)Nx;
        double var = g_sumsq[tid] / (double)Nx - mu * mu;
        float inv = rsqrtf((float)var + BN_EPS);
        float sc = gamma[tid] * inv;
        sScale[tid] = sc;
        sShift[tid] = beta[tid] - (float)mu * sc;
    }
    __syncthreads();
    int i = blockIdx.x * 256 + tid;
    if (i >= Nx) return;
    u64 x2[32];
    const float4* tr = reinterpret_cast<const float4*>(g_t + (size_t)i * NHID);
#pragma unroll
    for (int k = 0; k < 16; k++) {
        float4 v = tr[k];
        int k0 = k * 4;
        v.x = fmaxf(v.x * sScale[k0] + sShift[k0], 0.f);
        v.y = fmaxf(v.y * sScale[k0 + 1] + sShift[k0 + 1], 0.f);
        v.z = fmaxf(v.z * sScale[k0 + 2] + sShift[k0 + 2], 0.f);
        v.w = fmaxf(v.w * sScale[k0 + 3] + sShift[k0 + 3], 0.f);
        x2[2 * k] = pack2(v.x, v.y);
        x2[2 * k + 1] = pack2(v.z, v.w);
    }
    float dn = g_dn[Nold + i];
    float4* o = reinterpret_cast<float4*>(g_h + (size_t)(Nold + i) * NHID);
    for (int jg = 0; jg < 16; jg++) {
        float res[4];
#pragma unroll
        for (int jj = 0; jj < 4; jj++) {
            int j = jg * 4 + jj;
            u64 acc = pack2(sB[j], 0.f);
            const ulonglong2* wr = reinterpret_cast<const ulonglong2*>(sW + j * 64);
#pragma unroll
            for (int k = 0; k < 16; k++) {
                ulonglong2 wv = wr[k];
                fma2(acc, x2[2 * k], wv.x);
                fma2(acc, x2[2 * k + 1], wv.y);
            }
            float2 p = unpack2(acc);
            res[jj] = (p.x + p.y) * dn;
        }
        o[jg] = make_float4(res[0], res[1], res[2], res[3]);
    }
}

// ---------------- K6: persistent GRU, tf32 MMA with PRECONVERTED weights
// Blocks specialize by parity: even blocks = node rows/weights, odd = edge.
// smem: 2 matrices [192][68] of uint2 (tf32 hi,lo), then biases + heads.
#define SWU2_STRIDE 68
#define SWU2_MAT    (192 * SWU2_STRIDE)         // 13056 uint2
#define SMEM_U2     (2 * SWU2_MAT)              // 26112 uint2 = 208896 B
#define SMG_BYTES   (SMEM_U2 * 8 + 512 * 4)     // + 512 floats (bias/heads)

__global__ void __launch_bounds__(256) k_gru(
    const float* __restrict__ Wi_n, const float* __restrict__ bi_n,
    const float* __restrict__ Wh_n, const float* __restrict__ bh_n,
    const float* __restrict__ Wi_e, const float* __restrict__ bi_e,
    const float* __restrict__ Wh_e, const float* __restrict__ bh_e,
    const float* __restrict__ w_on, const float* __restrict__ b_on,
    const float* __restrict__ w_oe, const float* __restrict__ b_oe,
    int N, float* __restrict__ out) {
    extern __shared__ uint2 smu[];
    float* smf = reinterpret_cast<float*>(smu + SMEM_U2);
    int tid = threadIdx.x;
    int par = blockIdx.x & 1;          // 0 = node (even rows), 1 = edge (odd)
    const float* srcWi = par ? Wi_e : Wi_n;
    const float* srcWh = par ? Wh_e : Wh_n;
    const float* srcBi = par ? bi_e : bi_n;
    const float* srcBh = par ? bh_e : bh_n;
    // stage + preconvert weights to (hi,lo) tf32 pairs
    for (int s = tid; s < 2 * 12288; s += 256) {
        int mat = s / 12288, rem = s % 12288;
        int j = rem >> 6, k = rem & 63;
        const float* src = mat ? srcWh : srcWi;
        u32 hi, lo;
        cvt2(src[rem], hi, lo);
        smu[mat * SWU2_MAT + j * SWU2_STRIDE + k] = make_uint2(hi, lo);
    }
    if (tid < 192) {
        smf[tid] = srcBi[tid];
        smf[192 + tid] = srcBh[tid];
    }
    if (tid < 64) {
        smf[384 + tid] = w_on[tid];
        smf[448 + tid] = w_oe[tid];
    }
    __syncthreads();

    int wid = tid >> 5, lane = tid & 31;
    int g = lane >> 2, t = lane & 3;
    const float* mptr = par ? g_me : g_mn;
    const float* optr = par ? g_mn : g_me;
    const uint2* u2Wi = smu;
    const uint2* u2Wh = smu + SWU2_MAT;
    const float* sBi = smf;
    const float* sBh = smf + 192;
    const float* sWon = smf + 384;
    const float* sWoe = smf + 448;
    const float* gWi = par ? Wi_n : Wi_e;   // fallback: other type, global
    const float* gWh = par ? Wh_n : Wh_e;
    const float* gBi = par ? bi_n : bi_e;
    const float* gBh = par ? bh_n : bh_e;
    float* out_h = out + 2 * (size_t)N;
    float bon = b_on[0], boe = b_oe[0];

    int bi_ = blockIdx.x >> 1;
    int nb = gridDim.x >> 1;
    int K = (N - par + 1) / 2;    // rows with this parity

    u32 Amh[32], Aml[32], Ahh[32], Ahl[32];

    for (int kb = bi_ * 128; kb < K; kb += nb * 128) {
        int k0 = kb + wid * 16 + g;
        int k1 = k0 + 8;
        int r0 = 2 * k0 + par;
        int r1 = 2 * k1 + par;
        bool act0 = k0 < K, act1 = k1 < K;
        float dn0 = act0 ? g_dn[r0] : 0.f, de0 = act0 ? g_de[r0] : 0.f;
        float dn1 = act1 ? g_dn[r1] : 0.f, de1 = act1 ? g_de[r1] : 0.f;
        float scale0 = par ? de0 : dn0;
        float scale1 = par ? de1 : dn1;
        float oscale0 = par ? dn0 : de0;
        float oscale1 = par ? dn1 : de1;

        // load + convert A fragments (m and h) for all 8 k-tiles
#pragma unroll
        for (int kt = 0; kt < 8; kt++) {
            int c = kt * 8 + t;
            float v0 = act0 ? mptr[(size_t)r0 * 64 + c] : 0.f;
            float v1 = act1 ? mptr[(size_t)r1 * 64 + c] : 0.f;
            float v2 = act0 ? mptr[(size_t)r0 * 64 + c + 4] : 0.f;
            float v3 = act1 ? mptr[(size_t)r1 * 64 + c + 4] : 0.f;
            cvt2(v0, Amh[kt * 4 + 0], Aml[kt * 4 + 0]);
            cvt2(v1, Amh[kt * 4 + 1], Aml[kt * 4 + 1]);
            cvt2(v2, Amh[kt * 4 + 2], Aml[kt * 4 + 2]);
            cvt2(v3, Amh[kt * 4 + 3], Aml[kt * 4 + 3]);
            float w0 = act0 ? g_h[(size_t)r0 * 64 + c] : 0.f;
            float w1 = act1 ? g_h[(size_t)r1 * 64 + c] : 0.f;
            float w2 = act0 ? g_h[(size_t)r0 * 64 + c + 4] : 0.f;
            float w3 = act1 ? g_h[(size_t)r1 * 64 + c + 4] : 0.f;
            cvt2(w0, Ahh[kt * 4 + 0], Ahl[kt * 4 + 0]);
            cvt2(w1, Ahh[kt * 4 + 1], Ahl[kt * 4 + 1]);
            cvt2(w2, Ahh[kt * 4 + 2], Ahl[kt * 4 + 2]);
            cvt2(w3, Ahh[kt * 4 + 3], Ahl[kt * 4 + 3]);
        }

        float s_on0 = 0.f, s_oe0 = 0.f, s_on1 = 0.f, s_oe1 = 0.f;

        for (int q = 0; q < 8; q++) {
            float Dir[4] = {0,0,0,0}, Diz[4] = {0,0,0,0}, Din[4] = {0,0,0,0};
            float Dhr[4] = {0,0,0,0}, Dhz[4] = {0,0,0,0}, Dhn[4] = {0,0,0,0};
            int nr_ = (q * 8 + g) * SWU2_STRIDE;
            int nz_ = ((64 + q * 8) + g) * SWU2_STRIDE;
            int nn_ = ((128 + q * 8) + g) * SWU2_STRIDE;
#pragma unroll
            for (int kt = 0; kt < 8; kt++) {
                int kc = kt * 8 + t;
                uint2 B0, B1;
                // Wi: r gate
                B0 = u2Wi[nr_ + kc]; B1 = u2Wi[nr_ + kc + 4];
                mma_tf32(Dir, &Amh[kt * 4], B0.x, B1.x);
                mma_tf32(Dir, &Amh[kt * 4], B0.y, B1.y);
                mma_tf32(Dir, &Aml[kt * 4], B0.x, B1.x);
                // Wi: z gate
                B0 = u2Wi[nz_ + kc]; B1 = u2Wi[nz_ + kc + 4];
                mma_tf32(Diz, &Amh[kt * 4], B0.x, B1.x);
                mma_tf32(Diz, &Amh[kt * 4], B0.y, B1.y);
                mma_tf32(Diz, &Aml[kt * 4], B0.x, B1.x);
                // Wi: n gate
                B0 = u2Wi[nn_ + kc]; B1 = u2Wi[nn_ + kc + 4];
                mma_tf32(Din, &Amh[kt * 4], B0.x, B1.x);
                mma_tf32(Din, &Amh[kt * 4], B0.y, B1.y);
                mma_tf32(Din, &Aml[kt * 4], B0.x, B1.x);
                // Wh: r gate
                B0 = u2Wh[nr_ + kc]; B1 = u2Wh[nr_ + kc + 4];
                mma_tf32(Dhr, &Ahh[kt * 4], B0.x, B1.x);
                mma_tf32(Dhr, &Ahh[kt * 4], B0.y, B1.y);
                mma_tf32(Dhr, &Ahl[kt * 4], B0.x, B1.x);
                // Wh: z gate
                B0 = u2Wh[nz_ + kc]; B1 = u2Wh[nz_ + kc + 4];
                mma_tf32(Dhz, &Ahh[kt * 4], B0.x, B1.x);
                mma_tf32(Dhz, &Ahh[kt * 4], B0.y, B1.y);
                mma_tf32(Dhz, &Ahl[kt * 4], B0.x, B1.x);
                // Wh: n gate
                B0 = u2Wh[nn_ + kc]; B1 = u2Wh[nn_ + kc + 4];
                mma_tf32(Dhn, &Ahh[kt * 4], B0.x, B1.x);
                mma_tf32(Dhn, &Ahh[kt * 4], B0.y, B1.y);
                mma_tf32(Dhn, &Ahl[kt * 4], B0.x, B1.x);
            }
            // epilogue: rows (g -> r0: c0,c1), (g+8 -> r1: c2,c3); cols j0, j0+1
            int j0 = q * 8 + 2 * t;
            float2 hp0 = act0 ? *reinterpret_cast<const float2*>(g_h + (size_t)r0 * 64 + j0)
                              : make_float2(0.f, 0.f);
            float2 hp1 = act1 ? *reinterpret_cast<const float2*>(g_h + (size_t)r1 * 64 + j0)
                              : make_float2(0.f, 0.f);
            float hf[4];
#pragma unroll
            for (int e = 0; e < 4; e++) {
                int rowSel = e >> 1;
                int j = j0 + (e & 1);
                int ci = rowSel * 2 + (e & 1);
                float ir = Dir[ci] + sBi[j];
                float iz = Diz[ci] + sBi[64 + j];
                float in_ = Din[ci] + sBi[128 + j];
                float hr = Dhr[ci] + sBh[j];
                float hz = Dhz[ci] + sBh[64 + j];
                float hn = Dhn[ci] + sBh[128 + j];
                float hj = rowSel ? ((e & 1) ? hp1.y : hp1.x)
                                  : ((e & 1) ? hp0.y : hp0.x);
                float sc = rowSel ? scale1 : scale0;
                float r = sigmf(ir + hr);
                float z = sigmf(iz + hz);
                float ng = tanhfast(in_ + r * hn);
                hf[e] = sc * ((1.f - z) * ng + z * hj);
                float won = sWon[j], woe = sWoe[j];
                if (rowSel) { s_on1 += hf[e] * won; s_oe1 += hf[e] * woe; }
                else        { s_on0 += hf[e] * won; s_oe0 += hf[e] * woe; }
            }
            if (act0) *reinterpret_cast<float2*>(out_h + (size_t)r0 * 64 + j0) = make_float2(hf[0], hf[1]);
            if (act1) *reinterpret_cast<float2*>(out_h + (size_t)r1 * 64 + j0) = make_float2(hf[2], hf[3]);
        }

        // reduce head sums across the 4 lanes of each row group
        s_on0 += __shfl_xor_sync(0xffffffffu, s_on0, 1);
        s_on0 += __shfl_xor_sync(0xffffffffu, s_on0, 2);
        s_oe0 += __shfl_xor_sync(0xffffffffu, s_oe0, 1);
        s_oe0 += __shfl_xor_sync(0xffffffffu, s_oe0, 2);
        s_on1 += __shfl_xor_sync(0xffffffffu, s_on1, 1);
        s_on1 += __shfl_xor_sync(0xffffffffu, s_on1, 2);
        s_oe1 += __shfl_xor_sync(0xffffffffu, s_oe1, 1);
        s_oe1 += __shfl_xor_sync(0xffffffffu, s_oe1, 2);
        __syncwarp();

        if (t == 0) {
#pragma unroll
            for (int rowSel = 0; rowSel < 2; rowSel++) {
                int rr = rowSel ? r1 : r0;
                bool act = rowSel ? act1 : act0;
                if (!act) continue;
                float dnr = rowSel ? dn1 : dn0;
                float der = rowSel ? de1 : de0;
                float osc = rowSel ? oscale1 : oscale0;
                float son = rowSel ? s_on1 : s_on0;
                float soe = rowSel ? s_oe1 : s_oe0;
                if (osc != 0.f) {
                    // rare general fallback: add other-GRU contribution (scalar)
                    son = 0.f; soe = 0.f;
                    float ml[64], hl[64];
                    const float* mo = optr + (size_t)rr * 64;
                    const float* ho = g_h + (size_t)rr * 64;
                    for (int k = 0; k < 64; k++) { ml[k] = mo[k]; hl[k] = ho[k]; }
                    for (int j = 0; j < 64; j++) {
                        float ir = gBi[j], iz = gBi[64 + j], in_ = gBi[128 + j];
                        float hr = gBh[j], hz = gBh[64 + j], hn = gBh[128 + j];
                        for (int k = 0; k < 64; k++) {
                            ir += ml[k] * gWi[j * 64 + k];
                            iz += ml[k] * gWi[(64 + j) * 64 + k];
                            in_ += ml[k] * gWi[(128 + j) * 64 + k];
                            hr += hl[k] * gWh[j * 64 + k];
                            hz += hl[k] * gWh[(64 + j) * 64 + k];
                            hn += hl[k] * gWh[(128 + j) * 64 + k];
                        }
                        float r = sigmf(ir + hr);
                        float z = sigmf(iz + hz);
                        float ng = tanhfast(in_ + r * hn);
                        float hv = (1.f - z) * ng + z * hl[j];
                        size_t oi = (size_t)rr * 64 + j;
                        float hfv = out_h[oi] + osc * hv;
                        out_h[oi] = hfv;
                        son += hfv * sWon[j];
                        soe += hfv * sWoe[j];
                    }
                }
                float y = dnr * (son + bon) + der * (soe + boe);
                out[rr] = sigmf(y);
                out[(size_t)N + rr] = y;
            }
        }
    }
}

// ---------------- launch ----------------
extern "C" void kernel_launch(void* const* d_in, const int* in_sizes, int n_in,
                              void* d_out, int out_size) {
    const float* x     = (const float*)d_in[0];
    const float* h_in  = (const float*)d_in[1];
    const int*   nr    = (const int*)d_in[2];
    const int*   nc    = (const int*)d_in[3];
    const float* nv    = (const float*)d_in[4];
    const int*   er    = (const int*)d_in[5];
    const int*   ec    = (const int*)d_in[6];
    const float* ev    = (const float*)d_in[7];
    const float* W1    = (const float*)d_in[8];
    const float* b1    = (const float*)d_in[9];
    const float* gamma = (const float*)d_in[10];
    const float* beta  = (const float*)d_in[11];
    const float* W2    = (const float*)d_in[12];
    const float* b2    = (const float*)d_in[13];
    const float* Wi_n  = (const float*)d_in[14];
    const float* bi_n  = (const float*)d_in[15];
    const float* Wh_n  = (const float*)d_in[16];
    const float* bh_n  = (const float*)d_in[17];
    const float* Wi_e  = (const float*)d_in[18];
    const float* bi_e  = (const float*)d_in[19];
    const float* Wh_e  = (const float*)d_in[20];
    const float* bh_e  = (const float*)d_in[21];
    const float* w_on  = (const float*)d_in[22];
    const float* b_on  = (const float*)d_in[23];
    const float* w_oe  = (const float*)d_in[24];
    const float* b_oe  = (const float*)d_in[25];

    int Nx   = in_sizes[0] / NHID;
    int Nold = in_sizes[1] / NHID;
    int N    = Nx + Nold;
    int nnzN = in_sizes[2];
    int nnzE = in_sizes[5];
    float* out = (float*)d_out;

    cudaFuncSetAttribute(k_gru, cudaFuncAttributeMaxDynamicSharedMemorySize,
                         SMG_BYTES);

    k_init<<<1024, 256>>>((const float4*)h_in, Nold * (NHID / 4), N);

    int tot = nnzN + nnzE;
    k_hist<<<(tot + 255) / 256, 256>>>(nr, nc, nv, nnzN, er, ec, ev, nnzE);

    k_lin1<<<(Nx + 255) / 256, 256>>>(x, W1, b1, Nx);
    k_stats<<<256, 256>>>(Nx);
    k_lin2<<<(Nx + 255) / 256, 256>>>(gamma, beta, W2, b2, Nx, Nold);

    int nblk = (N + 4095) / 4096;
    {
        dim3 g1(nblk, 2);
        k_scan1<<<g1, 256>>>(N);
        k_scan2<<<2, 256>>>(nblk);
        dim3 g3(256, 2);
        k_scan3<<<g3, 256>>>(N);
    }

    k_scatter<<<(tot + 255) / 256, 256>>>(nr, nc, nv, nnzN, er, ec, ev, nnzE);

    {
        long long warps = 2LL * N;
        int blocks = (int)((warps * 32 + 255) / 256);
        k_spmm_csr<<<blocks, 256>>>(N);
    }

    k_gru<<<NSM, 256, SMG_BYTES>>>(
        Wi_n, bi_n, Wh_n, bh_n, Wi_e, bi_e, Wh_e, bh_e,
        w_on, b_on, w_oe, b_oe, N, out);
}